// round 1
// baseline (speedup 1.0000x reference)
#include <cuda_runtime.h>
#include <math.h>

// Problem constants: B=2, T=2048, C=1024, H=16, D=64
// Scratch in __device__ globals (allocation rules forbid cudaMalloc).
__device__ __align__(256) float g_Q[2u * 16 * 2048 * 64];  // [B,H,T,D]
__device__ __align__(256) float g_K[2u * 16 * 2048 * 64];
__device__ __align__(256) float g_V[2u * 16 * 2048 * 64];
__device__ __align__(256) float g_O[4096u * 1024];         // [B,T,C] attention output

// ---------------------------------------------------------------------------
// 128x128x16 register-blocked SGEMM: out[m][n] = sum_k A[m,k] * Wt[n,k] + bias[n]
// MODE 0: A = x, N=3072, epilogue scatters into g_Q/g_K/g_V as [B,H,T,D]
// MODE 1: A = g_O, N=1024, epilogue writes Out[m*1024+n]
// ---------------------------------------------------------------------------
template <int MODE>
__global__ void __launch_bounds__(256) gemm128(const float* __restrict__ Aext,
                                               const float* __restrict__ Wt,
                                               const float* __restrict__ bias,
                                               float* __restrict__ Out)
{
    const float* A = (MODE == 0) ? Aext : g_O;
    __shared__ float As[16][132];  // [k][m], pad 132 keeps float4 alignment, 2-way store conflicts
    __shared__ float Bs[16][132];  // [k][n]

    const int tid = threadIdx.x;
    const int m0 = blockIdx.y * 128;
    const int n0 = blockIdx.x * 128;
    const int rb = (tid >> 4) * 8;   // row base within tile
    const int cb = (tid & 15) * 8;   // col base within tile

    float acc[8][8];
#pragma unroll
    for (int i = 0; i < 8; i++)
#pragma unroll
        for (int j = 0; j < 8; j++) acc[i][j] = 0.f;

    for (int k0 = 0; k0 < 1024; k0 += 16) {
#pragma unroll
        for (int t = 0; t < 2; t++) {
            int lf = tid + t * 256;        // 0..511 float4 slots
            int row = lf >> 2;             // 0..127
            int c4 = (lf & 3) * 4;         // 0,4,8,12
            float4 av = *(const float4*)(A + (size_t)(m0 + row) * 1024 + k0 + c4);
            As[c4 + 0][row] = av.x;
            As[c4 + 1][row] = av.y;
            As[c4 + 2][row] = av.z;
            As[c4 + 3][row] = av.w;
            float4 bv = *(const float4*)(Wt + (size_t)(n0 + row) * 1024 + k0 + c4);
            Bs[c4 + 0][row] = bv.x;
            Bs[c4 + 1][row] = bv.y;
            Bs[c4 + 2][row] = bv.z;
            Bs[c4 + 3][row] = bv.w;
        }
        __syncthreads();
#pragma unroll
        for (int k = 0; k < 16; k++) {
            float a[8], b[8];
            *(float4*)&a[0] = *(const float4*)&As[k][rb];
            *(float4*)&a[4] = *(const float4*)&As[k][rb + 4];
            *(float4*)&b[0] = *(const float4*)&Bs[k][cb];
            *(float4*)&b[4] = *(const float4*)&Bs[k][cb + 4];
#pragma unroll
            for (int i = 0; i < 8; i++)
#pragma unroll
                for (int j = 0; j < 8; j++) acc[i][j] = fmaf(a[i], b[j], acc[i][j]);
        }
        __syncthreads();
    }

    if (MODE == 0) {
        // scatter qkv: n in [0,1024)->Q, [1024,2048)->K, [2048,3072)->V, layout [B,H,T,D]
#pragma unroll
        for (int i = 0; i < 8; i++) {
            int m = m0 + rb + i;
            int bb = m >> 11;      // batch
            int tt = m & 2047;     // token
#pragma unroll
            for (int j = 0; j < 8; j++) {
                int n = n0 + cb + j;
                float v = acc[i][j] + bias[n];
                int which = n >> 10;
                int cc = n & 1023;
                int hh = cc >> 6;
                int dd = cc & 63;
                float* dst = (which == 0) ? g_Q : (which == 1) ? g_K : g_V;
                dst[(((size_t)bb * 16 + hh) * 2048 + tt) * 64 + dd] = v;
            }
        }
    } else {
#pragma unroll
        for (int i = 0; i < 8; i++) {
            int m = m0 + rb + i;
#pragma unroll
            for (int j = 0; j < 8; j++) {
                int n = n0 + cb + j;
                Out[(size_t)m * 1024 + n] = acc[i][j] + bias[n];
            }
        }
    }
}

// ---------------------------------------------------------------------------
// Flash-attention style causal attention.
// Grid: (32 q-tiles, 32 b*h). Block: 256 threads = 16x16; each thread owns a
// 4x4 S tile and a 4-row x 4-dim O tile. Row softmax stats reduced across the
// 16 tx-lanes of each half-warp via shfl.
// ---------------------------------------------------------------------------
#define SP 68  // smem row stride (floats): 68*4B = 17*16B -> float4-aligned, breaks worst conflicts

__global__ void __launch_bounds__(256) attn_kernel()
{
    extern __shared__ float sm[];
    float* Qs = sm;                // [64 d][SP] transposed: Qs[d*SP + q]
    float* Ks = sm + 64 * SP;      // [64 d][SP] transposed: Ks[d*SP + kk]
    float* Vs = sm + 2 * 64 * SP;  // [64 kk][SP] natural:   Vs[kk*SP + d]
    float* Ps = sm + 3 * 64 * SP;  // [64 q][SP]:            Ps[q*SP + kk]

    const int tid = threadIdx.x;
    const int qt = blockIdx.x;     // query tile (64 rows)
    const int bh = blockIdx.y;     // b*16 + h
    const float* Qg = g_Q + (size_t)bh * 2048 * 64;
    const float* Kg = g_K + (size_t)bh * 2048 * 64;
    const float* Vg = g_V + (size_t)bh * 2048 * 64;

    const int ty = tid >> 4, tx = tid & 15;
    const int r0 = ty * 4, c0 = tx * 4;

    // Load Q tile transposed: Qs[d][q]
#pragma unroll
    for (int t = 0; t < 4; t++) {
        int lf = tid + t * 256;          // 0..1023 float4 slots
        int q = lf >> 4;                 // 0..63
        int d4 = (lf & 15) * 4;          // 0..60
        float4 v = *(const float4*)(Qg + (size_t)(qt * 64 + q) * 64 + d4);
        Qs[(d4 + 0) * SP + q] = v.x;
        Qs[(d4 + 1) * SP + q] = v.y;
        Qs[(d4 + 2) * SP + q] = v.z;
        Qs[(d4 + 3) * SP + q] = v.w;
    }

    float o[4][4];
    float mrow[4], lrow[4];
#pragma unroll
    for (int i = 0; i < 4; i++) {
        mrow[i] = -INFINITY;
        lrow[i] = 0.f;
#pragma unroll
        for (int j = 0; j < 4; j++) o[i][j] = 0.f;
    }

    for (int kt = 0; kt <= qt; kt++) {
        // Load K tile transposed + V tile natural
#pragma unroll
        for (int t = 0; t < 4; t++) {
            int lf = tid + t * 256;
            int kk = lf >> 4;
            int d4 = (lf & 15) * 4;
            float4 kv = *(const float4*)(Kg + (size_t)(kt * 64 + kk) * 64 + d4);
            Ks[(d4 + 0) * SP + kk] = kv.x;
            Ks[(d4 + 1) * SP + kk] = kv.y;
            Ks[(d4 + 2) * SP + kk] = kv.z;
            Ks[(d4 + 3) * SP + kk] = kv.w;
            float4 vv = *(const float4*)(Vg + (size_t)(kt * 64 + kk) * 64 + d4);
            *(float4*)(Vs + kk * SP + d4) = vv;
        }
        __syncthreads();

        // S = Q K^T (4x4 per thread), accumulate over d
        float s[4][4];
#pragma unroll
        for (int i = 0; i < 4; i++)
#pragma unroll
            for (int j = 0; j < 4; j++) s[i][j] = 0.f;

#pragma unroll 16
        for (int d = 0; d < 64; d++) {
            float4 qv = *(const float4*)(Qs + d * SP + r0);  // broadcast within half-warp
            float4 kv = *(const float4*)(Ks + d * SP + c0);  // contiguous across lanes
            float qa[4] = {qv.x, qv.y, qv.z, qv.w};
            float ka[4] = {kv.x, kv.y, kv.z, kv.w};
#pragma unroll
            for (int i = 0; i < 4; i++)
#pragma unroll
                for (int j = 0; j < 4; j++) s[i][j] = fmaf(qa[i], ka[j], s[i][j]);
        }

        const bool diag = (kt == qt);
#pragma unroll
        for (int i = 0; i < 4; i++) {
#pragma unroll
            for (int j = 0; j < 4; j++) {
                float sv = s[i][j] * 0.125f;  // 1/sqrt(64)
                if (diag && (c0 + j > r0 + i)) sv = -INFINITY;  // tile offsets cancel
                s[i][j] = sv;
            }
            // row max across this thread's 4 cols, then across the 16 tx lanes
            float rm = fmaxf(fmaxf(s[i][0], s[i][1]), fmaxf(s[i][2], s[i][3]));
#pragma unroll
            for (int off = 8; off > 0; off >>= 1)
                rm = fmaxf(rm, __shfl_xor_sync(0xffffffffu, rm, off));
            float mnew = fmaxf(mrow[i], rm);
            float esc = __expf(mrow[i] - mnew);  // first iter: exp(-inf - finite) = 0
            float p0 = __expf(s[i][0] - mnew);
            float p1 = __expf(s[i][1] - mnew);
            float p2 = __expf(s[i][2] - mnew);
            float p3 = __expf(s[i][3] - mnew);
            *(float4*)(Ps + (r0 + i) * SP + c0) = make_float4(p0, p1, p2, p3);
            float rs = p0 + p1 + p2 + p3;
#pragma unroll
            for (int off = 8; off > 0; off >>= 1)
                rs += __shfl_xor_sync(0xffffffffu, rs, off);
            lrow[i] = lrow[i] * esc + rs;
            mrow[i] = mnew;
#pragma unroll
            for (int j = 0; j < 4; j++) o[i][j] *= esc;
        }
        __syncthreads();

        // O += P V  (thread's 4 rows x 4 dims)
#pragma unroll 8
        for (int kk = 0; kk < 64; kk++) {
            float4 vv = *(const float4*)(Vs + kk * SP + c0);
#pragma unroll
            for (int i = 0; i < 4; i++) {
                float pi = Ps[(r0 + i) * SP + kk];  // broadcast within half-warp
                o[i][0] = fmaf(pi, vv.x, o[i][0]);
                o[i][1] = fmaf(pi, vv.y, o[i][1]);
                o[i][2] = fmaf(pi, vv.z, o[i][2]);
                o[i][3] = fmaf(pi, vv.w, o[i][3]);
            }
        }
        __syncthreads();
    }

    // Normalize and write to g_O as [B,T,C] (c = h*64 + d)
    const int b = bh >> 4, h = bh & 15;
#pragma unroll
    for (int i = 0; i < 4; i++) {
        float inv = 1.f / lrow[i];
        int q = qt * 64 + r0 + i;
        float4 v = make_float4(o[i][0] * inv, o[i][1] * inv, o[i][2] * inv, o[i][3] * inv);
        *(float4*)(g_O + ((size_t)b * 2048 + q) * 1024 + h * 64 + c0) = v;
    }
}

// ---------------------------------------------------------------------------
extern "C" void kernel_launch(void* const* d_in, const int* in_sizes, int n_in,
                              void* d_out, int out_size)
{
    const float* x     = (const float*)d_in[0];  // [2,2048,1024]
    const float* qkv_w = (const float*)d_in[1];  // [3072,1024]
    const float* qkv_b = (const float*)d_in[2];  // [3072]
    const float* out_w = (const float*)d_in[3];  // [1024,1024]
    const float* out_b = (const float*)d_in[4];  // [1024]
    float* out = (float*)d_out;                  // [2,2048,1024]

    // 1) QKV projection + scatter to [B,H,T,D]
    gemm128<0><<<dim3(24, 32), 256>>>(x, qkv_w, qkv_b, nullptr);

    // 2) Causal flash attention -> g_O [B,T,C]
    const int smem_bytes = 4 * 64 * SP * (int)sizeof(float);  // 69,632 B
    cudaFuncSetAttribute(attn_kernel, cudaFuncAttributeMaxDynamicSharedMemorySize, smem_bytes);
    attn_kernel<<<dim3(32, 32), 256, smem_bytes>>>();

    // 3) Output projection -> d_out
    gemm128<1><<<dim3(8, 32), 256>>>(nullptr, out_w, out_b, out);
}

// round 3
// speedup vs baseline: 1.3542x; 1.3542x over previous
#include <cuda_runtime.h>
#include <math.h>
#include <stdint.h>

// Problem constants: B=2, T=2048, C=1024, H=16, D=64
__device__ __align__(256) float g_Q[2u * 16 * 2048 * 64];  // [B,H,T,D]
__device__ __align__(256) float g_K[2u * 16 * 2048 * 64];
__device__ __align__(256) float g_V[2u * 16 * 2048 * 64];
__device__ __align__(256) float g_O[4096u * 1024];         // [B,T,C]

// ---------------------------------------------------------------------------
// tf32 helpers
// ---------------------------------------------------------------------------
__device__ __forceinline__ uint32_t f2tf(float x) {
    uint32_t r;
    asm("cvt.rna.tf32.f32 %0, %1;" : "=r"(r) : "f"(x));
    return r;
}
__device__ __forceinline__ void tf32split(float x, uint32_t& h, uint32_t& l) {
    h = f2tf(x);
    l = f2tf(x - __uint_as_float(h));
}
// D += A*B  (m16n8k8, tf32 inputs, fp32 accum)
__device__ __forceinline__ void mma8(float* d, const uint32_t* a, const uint32_t* b) {
    asm volatile(
        "mma.sync.aligned.m16n8k8.row.col.f32.tf32.tf32.f32 "
        "{%0,%1,%2,%3},{%4,%5,%6,%7},{%8,%9},{%0,%1,%2,%3};"
        : "+f"(d[0]), "+f"(d[1]), "+f"(d[2]), "+f"(d[3])
        : "r"(a[0]), "r"(a[1]), "r"(a[2]), "r"(a[3]), "r"(b[0]), "r"(b[1]));
}

// ---------------------------------------------------------------------------
// 3xTF32 GEMM: out[m][n] = sum_k A[m,k]*Wt[n,k] + bias[n]
// Block 128x128, BK=16, 8 warps (2m x 4n), warp tile 64x32.
// MODE 0: A = x, epilogue scatters to g_Q/g_K/g_V [B,H,T,D]
// MODE 1: A = g_O, epilogue writes Out
// ---------------------------------------------------------------------------
template <int MODE>
__global__ void __launch_bounds__(256, 1) gemm_tf32(const float* __restrict__ Aext,
                                                    const float* __restrict__ Wt,
                                                    const float* __restrict__ bias,
                                                    float* __restrict__ Out)
{
    const float* A = (MODE == 0) ? Aext : g_O;
    __shared__ float As[2][128][20];  // stride 20 -> conflict-free frag reads
    __shared__ float Bs[2][128][20];

    const int tid = threadIdx.x;
    const int m0 = blockIdx.y * 128, n0 = blockIdx.x * 128;
    const int warp = tid >> 5, lane = tid & 31;
    const int wm = (warp >> 2) * 64, wn = (warp & 3) * 32;
    const int g = lane >> 2, tq = lane & 3;

    float acc[4][4][4];
#pragma unroll
    for (int mt = 0; mt < 4; mt++)
#pragma unroll
        for (int nt = 0; nt < 4; nt++)
#pragma unroll
            for (int r = 0; r < 4; r++) acc[mt][nt][r] = 0.f;

    // stage 0
#pragma unroll
    for (int t = 0; t < 2; t++) {
        int lf = tid + t * 256, row = lf >> 2, c4 = (lf & 3) * 4;
        *(float4*)&As[0][row][c4] = *(const float4*)(A + (size_t)(m0 + row) * 1024 + c4);
        *(float4*)&Bs[0][row][c4] = *(const float4*)(Wt + (size_t)(n0 + row) * 1024 + c4);
    }
    __syncthreads();

    for (int kt = 0; kt < 64; kt++) {
        const int buf = kt & 1;
        float4 ra[2], rb[2];
        if (kt < 63) {
            int k0 = (kt + 1) * 16;
#pragma unroll
            for (int t = 0; t < 2; t++) {
                int lf = tid + t * 256, row = lf >> 2, c4 = (lf & 3) * 4;
                ra[t] = *(const float4*)(A + (size_t)(m0 + row) * 1024 + k0 + c4);
                rb[t] = *(const float4*)(Wt + (size_t)(n0 + row) * 1024 + k0 + c4);
            }
        }
#pragma unroll
        for (int ks = 0; ks < 2; ks++) {
            const int kb = ks * 8;
            uint32_t Ah[4][4], Al[4][4];
#pragma unroll
            for (int mt = 0; mt < 4; mt++) {
                int r0 = wm + mt * 16 + g;
                tf32split(As[buf][r0][kb + tq],         Ah[mt][0], Al[mt][0]);
                tf32split(As[buf][r0 + 8][kb + tq],     Ah[mt][1], Al[mt][1]);
                tf32split(As[buf][r0][kb + tq + 4],     Ah[mt][2], Al[mt][2]);
                tf32split(As[buf][r0 + 8][kb + tq + 4], Ah[mt][3], Al[mt][3]);
            }
            uint32_t Bh[4][2], Bl[4][2];
#pragma unroll
            for (int nt = 0; nt < 4; nt++) {
                int c0r = wn + nt * 8 + g;
                tf32split(Bs[buf][c0r][kb + tq],     Bh[nt][0], Bl[nt][0]);
                tf32split(Bs[buf][c0r][kb + tq + 4], Bh[nt][1], Bl[nt][1]);
            }
#pragma unroll
            for (int mt = 0; mt < 4; mt++)
#pragma unroll
                for (int nt = 0; nt < 4; nt++) {
                    mma8(acc[mt][nt], Ah[mt], Bh[nt]);
                    mma8(acc[mt][nt], Al[mt], Bh[nt]);
                    mma8(acc[mt][nt], Ah[mt], Bl[nt]);
                }
        }
        if (kt < 63) {
#pragma unroll
            for (int t = 0; t < 2; t++) {
                int lf = tid + t * 256, row = lf >> 2, c4 = (lf & 3) * 4;
                *(float4*)&As[buf ^ 1][row][c4] = ra[t];
                *(float4*)&Bs[buf ^ 1][row][c4] = rb[t];
            }
            __syncthreads();
        }
    }

    // epilogue: c-frag r: 0=(row,2tq) 1=(row,2tq+1) 2=(row+8,2tq) 3=(row+8,2tq+1)
#pragma unroll
    for (int mt = 0; mt < 4; mt++) {
#pragma unroll
        for (int rr = 0; rr < 2; rr++) {
            int m = m0 + wm + mt * 16 + g + rr * 8;
#pragma unroll
            for (int nt = 0; nt < 4; nt++) {
#pragma unroll
                for (int cc = 0; cc < 2; cc++) {
                    int n = n0 + wn + nt * 8 + tq * 2 + cc;
                    float v = acc[mt][nt][rr * 2 + cc] + bias[n];
                    if (MODE == 0) {
                        int bb = m >> 11, tt = m & 2047;
                        int which = n >> 10, c = n & 1023, hh = c >> 6, dd = c & 63;
                        float* dst = (which == 0) ? g_Q : (which == 1) ? g_K : g_V;
                        dst[(((size_t)bb * 16 + hh) * 2048 + tt) * 64 + dd] = v;
                    } else {
                        Out[(size_t)m * 1024 + n] = v;
                    }
                }
            }
        }
    }
}

// ---------------------------------------------------------------------------
// Flash attention with 3xTF32 mma. Block = 128 threads (4 warps), 64 q-rows.
// Warp w owns q-rows [16w,16w+16): S (m16 x n64), softmax on fragments,
// P via smem re-fragmentation, O += P V (m16 x n64 over d).
// ---------------------------------------------------------------------------
#define SQ 68  // Qs/Ks/Ps stride: (g*68+tq)%32 = 4g+tq -> conflict-free
#define SV 72  // Vs stride: (tq*72+g)%32 = 8tq+g -> conflict-free

__global__ void __launch_bounds__(128) attn_tf32()
{
    extern __shared__ float sm[];
    float* Qs = sm;             // [64][SQ]
    float* Ks = Qs + 64 * SQ;   // [64][SQ]
    float* Vs = Ks + 64 * SQ;   // [64][SV]
    float* Ps = Vs + 64 * SV;   // [64][SQ]

    const int tid = threadIdx.x;
    const int qt = blockIdx.x, bh = blockIdx.y;
    const float* Qg = g_Q + (size_t)bh * 2048 * 64;
    const float* Kg = g_K + (size_t)bh * 2048 * 64;
    const float* Vg = g_V + (size_t)bh * 2048 * 64;

    const int warp = tid >> 5, lane = tid & 31;
    const int g = lane >> 2, tq = lane & 3;
    const int qrow0 = warp * 16 + g;  // local q-row for c-frag r=0

    // load Q tile [64][64]
#pragma unroll
    for (int t = 0; t < 8; t++) {
        int lf = tid + t * 128, q = lf >> 4, d4 = (lf & 15) * 4;
        *(float4*)&Qs[q * SQ + d4] = *(const float4*)(Qg + (size_t)(qt * 64 + q) * 64 + d4);
    }

    float ofrag[8][4];
#pragma unroll
    for (int nt = 0; nt < 8; nt++)
#pragma unroll
        for (int r = 0; r < 4; r++) ofrag[nt][r] = 0.f;
    float mrow[2] = {-INFINITY, -INFINITY}, lrow[2] = {0.f, 0.f};

    for (int kt = 0; kt <= qt; kt++) {
        __syncthreads();  // Ks/Vs safe to overwrite (also orders Qs load at kt=0)
#pragma unroll
        for (int t = 0; t < 8; t++) {
            int lf = tid + t * 128, kk = lf >> 4, d4 = (lf & 15) * 4;
            *(float4*)&Ks[kk * SQ + d4] = *(const float4*)(Kg + (size_t)(kt * 64 + kk) * 64 + d4);
            *(float4*)&Vs[kk * SV + d4] = *(const float4*)(Vg + (size_t)(kt * 64 + kk) * 64 + d4);
        }
        __syncthreads();

        // S = Q K^T
        float sfrag[8][4];
#pragma unroll
        for (int nt = 0; nt < 8; nt++)
#pragma unroll
            for (int r = 0; r < 4; r++) sfrag[nt][r] = 0.f;

#pragma unroll
        for (int k8 = 0; k8 < 8; k8++) {
            int kb = k8 * 8;
            uint32_t ah[4], al[4];
            tf32split(Qs[qrow0 * SQ + kb + tq],           ah[0], al[0]);
            tf32split(Qs[(qrow0 + 8) * SQ + kb + tq],     ah[1], al[1]);
            tf32split(Qs[qrow0 * SQ + kb + tq + 4],       ah[2], al[2]);
            tf32split(Qs[(qrow0 + 8) * SQ + kb + tq + 4], ah[3], al[3]);
#pragma unroll
            for (int nt = 0; nt < 8; nt++) {
                uint32_t bhh[2], bll[2];
                tf32split(Ks[(nt * 8 + g) * SQ + kb + tq],     bhh[0], bll[0]);
                tf32split(Ks[(nt * 8 + g) * SQ + kb + tq + 4], bhh[1], bll[1]);
                mma8(sfrag[nt], ah, bhh);
                mma8(sfrag[nt], al, bhh);
                mma8(sfrag[nt], ah, bll);
            }
        }

        // softmax on fragments (rows qrow0, qrow0+8; row spread over 4 tq lanes)
        const bool diag = (kt == qt);
#pragma unroll
        for (int r = 0; r < 2; r++) {
            int lq = qrow0 + r * 8;
            float rm = -INFINITY;
#pragma unroll
            for (int nt = 0; nt < 8; nt++) {
#pragma unroll
                for (int cc = 0; cc < 2; cc++) {
                    float sv = sfrag[nt][r * 2 + cc] * 0.125f;  // 1/sqrt(64)
                    int lk = nt * 8 + tq * 2 + cc;
                    if (diag && lk > lq) sv = -INFINITY;
                    sfrag[nt][r * 2 + cc] = sv;
                    rm = fmaxf(rm, sv);
                }
            }
            rm = fmaxf(rm, __shfl_xor_sync(0xffffffffu, rm, 1));
            rm = fmaxf(rm, __shfl_xor_sync(0xffffffffu, rm, 2));
            float mnew = fmaxf(mrow[r], rm);
            float esc = __expf(mrow[r] - mnew);
            float rs = 0.f;
#pragma unroll
            for (int nt = 0; nt < 8; nt++) {
                float p0 = __expf(sfrag[nt][r * 2] - mnew);
                float p1 = __expf(sfrag[nt][r * 2 + 1] - mnew);
                *(float2*)&Ps[lq * SQ + nt * 8 + tq * 2] = make_float2(p0, p1);
                rs += p0 + p1;
            }
            rs += __shfl_xor_sync(0xffffffffu, rs, 1);
            rs += __shfl_xor_sync(0xffffffffu, rs, 2);
            lrow[r] = lrow[r] * esc + rs;
            mrow[r] = mnew;
#pragma unroll
            for (int nt = 0; nt < 8; nt++) {
                ofrag[nt][r * 2] *= esc;
                ofrag[nt][r * 2 + 1] *= esc;
            }
        }
        __syncwarp();  // P rows are warp-private: warp-level visibility suffices

        // O += P V
#pragma unroll
        for (int k8 = 0; k8 < 8; k8++) {
            int kb = k8 * 8;
            uint32_t ah[4], al[4];
            tf32split(Ps[qrow0 * SQ + kb + tq],           ah[0], al[0]);
            tf32split(Ps[(qrow0 + 8) * SQ + kb + tq],     ah[1], al[1]);
            tf32split(Ps[qrow0 * SQ + kb + tq + 4],       ah[2], al[2]);
            tf32split(Ps[(qrow0 + 8) * SQ + kb + tq + 4], ah[3], al[3]);
#pragma unroll
            for (int nt = 0; nt < 8; nt++) {
                uint32_t bhh[2], bll[2];
                tf32split(Vs[(kb + tq) * SV + nt * 8 + g],     bhh[0], bll[0]);
                tf32split(Vs[(kb + tq + 4) * SV + nt * 8 + g], bhh[1], bll[1]);
                mma8(ofrag[nt], ah, bhh);
                mma8(ofrag[nt], al, bhh);
                mma8(ofrag[nt], ah, bll);
            }
        }
    }

    // normalize + write [B,T,C]
    const int b = bh >> 4, h = bh & 15;
#pragma unroll
    for (int r = 0; r < 2; r++) {
        float inv = 1.f / lrow[r];
        int q = qt * 64 + qrow0 + r * 8;
#pragma unroll
        for (int nt = 0; nt < 8; nt++) {
            float2 v = make_float2(ofrag[nt][r * 2] * inv, ofrag[nt][r * 2 + 1] * inv);
            *(float2*)&g_O[((size_t)b * 2048 + q) * 1024 + h * 64 + nt * 8 + tq * 2] = v;
        }
    }
}

// ---------------------------------------------------------------------------
extern "C" void kernel_launch(void* const* d_in, const int* in_sizes, int n_in,
                              void* d_out, int out_size)
{
    const float* x     = (const float*)d_in[0];
    const float* qkv_w = (const float*)d_in[1];
    const float* qkv_b = (const float*)d_in[2];
    const float* out_w = (const float*)d_in[3];
    const float* out_b = (const float*)d_in[4];
    float* out = (float*)d_out;

    gemm_tf32<0><<<dim3(24, 32), 256>>>(x, qkv_w, qkv_b, nullptr);

    const int smem_bytes = (64 * SQ * 3 + 64 * SV) * (int)sizeof(float);  // 70,656 B
    cudaFuncSetAttribute(attn_tf32, cudaFuncAttributeMaxDynamicSharedMemorySize, smem_bytes);
    attn_tf32<<<dim3(32, 32), 128, smem_bytes>>>();

    gemm_tf32<1><<<dim3(8, 32), 256>>>(nullptr, out_w, out_b, out);
}

// round 4
// speedup vs baseline: 1.8809x; 1.3889x over previous
#include <cuda_runtime.h>
#include <cuda_bf16.h>
#include <math.h>
#include <stdint.h>

// Problem constants: B=2, T=2048, C=1024, H=16, D=64
__device__ __align__(256) float g_Q[2u * 16 * 2048 * 64];  // [B,H,T,D]
__device__ __align__(256) float g_K[2u * 16 * 2048 * 64];
__device__ __align__(256) float g_V[2u * 16 * 2048 * 64];
__device__ __align__(256) float g_O[4096u * 1024];         // [B,T,C]

typedef __nv_bfloat16 bf16;

// ---------------------------------------------------------------------------
// helpers
// ---------------------------------------------------------------------------
__device__ __forceinline__ void bfsplit(float x, bf16& h, bf16& l) {
    h = __float2bfloat16(x);
    l = __float2bfloat16(x - __bfloat162float(h));
}
// split a float4 and store 4 hi + 4 lo bf16 (8B each, aligned)
__device__ __forceinline__ void split4(bf16* ph, bf16* pl, float4 v) {
    bf16 h[4], l[4];
    bfsplit(v.x, h[0], l[0]); bfsplit(v.y, h[1], l[1]);
    bfsplit(v.z, h[2], l[2]); bfsplit(v.w, h[3], l[3]);
    *(uint2*)ph = *(const uint2*)h;
    *(uint2*)pl = *(const uint2*)l;
}
// D += A*B  (m16n8k16, bf16 inputs, fp32 accum)
__device__ __forceinline__ void mma16(float* d, const uint32_t* a, const uint32_t* b) {
    asm volatile(
        "mma.sync.aligned.m16n8k16.row.col.f32.bf16.bf16.f32 "
        "{%0,%1,%2,%3},{%4,%5,%6,%7},{%8,%9},{%0,%1,%2,%3};"
        : "+f"(d[0]), "+f"(d[1]), "+f"(d[2]), "+f"(d[3])
        : "r"(a[0]), "r"(a[1]), "r"(a[2]), "r"(a[3]), "r"(b[0]), "r"(b[1]));
}
__device__ __forceinline__ uint32_t packbf2(float a, float b, float& la, float& lb) {
    union { bf16 h[2]; uint32_t u; } c;
    c.h[0] = __float2bfloat16(a);
    c.h[1] = __float2bfloat16(b);
    la = a - __bfloat162float(c.h[0]);
    lb = b - __bfloat162float(c.h[1]);
    return c.u;
}

// ---------------------------------------------------------------------------
// 3xBF16-split GEMM: out[m][n] = sum_k A[m,k]*Wt[n,k] + bias[n]
// Block 128x128, BK=16, 8 warps (2m x 4n), warp tile 64x32.
// Smem holds pre-split bf16 hi/lo planes; fragments are single 32-bit LDS.
// MODE 0: A = x, epilogue scatters to g_Q/g_K/g_V [B,H,T,D]
// MODE 1: A = g_O, epilogue writes Out
// ---------------------------------------------------------------------------
#define GS 24  // bf16 row stride: word stride 12 -> g*12+tq distinct mod 32

template <int MODE>
__global__ void __launch_bounds__(256, 1) gemm_bf16(const float* __restrict__ Aext,
                                                    const float* __restrict__ Wt,
                                                    const float* __restrict__ bias,
                                                    float* __restrict__ Out)
{
    const float* A = (MODE == 0) ? Aext : g_O;
    __shared__ bf16 Ah[2][128][GS], Al[2][128][GS];
    __shared__ bf16 Bh[2][128][GS], Bl[2][128][GS];  // 48KB total

    const int tid = threadIdx.x;
    const int m0 = blockIdx.y * 128, n0 = blockIdx.x * 128;
    const int warp = tid >> 5, lane = tid & 31;
    const int wm = (warp >> 2) * 64, wn = (warp & 3) * 32;
    const int g = lane >> 2, tq = lane & 3;

    float acc[4][4][4];
#pragma unroll
    for (int mt = 0; mt < 4; mt++)
#pragma unroll
        for (int nt = 0; nt < 4; nt++)
#pragma unroll
            for (int r = 0; r < 4; r++) acc[mt][nt][r] = 0.f;

    // stage 0
#pragma unroll
    for (int t = 0; t < 2; t++) {
        int lf = tid + t * 256, row = lf >> 2, c4 = (lf & 3) * 4;
        split4(&Ah[0][row][c4], &Al[0][row][c4],
               *(const float4*)(A + (size_t)(m0 + row) * 1024 + c4));
        split4(&Bh[0][row][c4], &Bl[0][row][c4],
               *(const float4*)(Wt + (size_t)(n0 + row) * 1024 + c4));
    }
    __syncthreads();

    for (int kt = 0; kt < 64; kt++) {
        const int buf = kt & 1;
        float4 ra[2], rb[2];
        if (kt < 63) {
            int k0 = (kt + 1) * 16;
#pragma unroll
            for (int t = 0; t < 2; t++) {
                int lf = tid + t * 256, row = lf >> 2, c4 = (lf & 3) * 4;
                ra[t] = *(const float4*)(A + (size_t)(m0 + row) * 1024 + k0 + c4);
                rb[t] = *(const float4*)(Wt + (size_t)(n0 + row) * 1024 + k0 + c4);
            }
        }
        // fragment loads (single b32 each)
        uint32_t Ahf[4][4], Alf[4][4];
#pragma unroll
        for (int mt = 0; mt < 4; mt++) {
            int r0 = wm + mt * 16 + g;
            Ahf[mt][0] = *(const uint32_t*)&Ah[buf][r0][2 * tq];
            Ahf[mt][1] = *(const uint32_t*)&Ah[buf][r0 + 8][2 * tq];
            Ahf[mt][2] = *(const uint32_t*)&Ah[buf][r0][2 * tq + 8];
            Ahf[mt][3] = *(const uint32_t*)&Ah[buf][r0 + 8][2 * tq + 8];
            Alf[mt][0] = *(const uint32_t*)&Al[buf][r0][2 * tq];
            Alf[mt][1] = *(const uint32_t*)&Al[buf][r0 + 8][2 * tq];
            Alf[mt][2] = *(const uint32_t*)&Al[buf][r0][2 * tq + 8];
            Alf[mt][3] = *(const uint32_t*)&Al[buf][r0 + 8][2 * tq + 8];
        }
        uint32_t Bhf[4][2], Blf[4][2];
#pragma unroll
        for (int nt = 0; nt < 4; nt++) {
            int c0r = wn + nt * 8 + g;
            Bhf[nt][0] = *(const uint32_t*)&Bh[buf][c0r][2 * tq];
            Bhf[nt][1] = *(const uint32_t*)&Bh[buf][c0r][2 * tq + 8];
            Blf[nt][0] = *(const uint32_t*)&Bl[buf][c0r][2 * tq];
            Blf[nt][1] = *(const uint32_t*)&Bl[buf][c0r][2 * tq + 8];
        }
#pragma unroll
        for (int mt = 0; mt < 4; mt++)
#pragma unroll
            for (int nt = 0; nt < 4; nt++) {
                mma16(acc[mt][nt], Ahf[mt], Bhf[nt]);
                mma16(acc[mt][nt], Alf[mt], Bhf[nt]);
                mma16(acc[mt][nt], Ahf[mt], Blf[nt]);
            }
        if (kt < 63) {
            __syncthreads();
#pragma unroll
            for (int t = 0; t < 2; t++) {
                int lf = tid + t * 256, row = lf >> 2, c4 = (lf & 3) * 4;
                split4(&Ah[buf ^ 1][row][c4], &Al[buf ^ 1][row][c4], ra[t]);
                split4(&Bh[buf ^ 1][row][c4], &Bl[buf ^ 1][row][c4], rb[t]);
            }
            __syncthreads();
        }
    }

    // epilogue: c-frag r: 0=(row,2tq) 1=(row,2tq+1) 2=(row+8,2tq) 3=(row+8,2tq+1)
#pragma unroll
    for (int mt = 0; mt < 4; mt++) {
#pragma unroll
        for (int rr = 0; rr < 2; rr++) {
            int m = m0 + wm + mt * 16 + g + rr * 8;
#pragma unroll
            for (int nt = 0; nt < 4; nt++) {
#pragma unroll
                for (int cc = 0; cc < 2; cc++) {
                    int n = n0 + wn + nt * 8 + tq * 2 + cc;
                    float v = acc[mt][nt][rr * 2 + cc] + bias[n];
                    if (MODE == 0) {
                        int bb = m >> 11, tt = m & 2047;
                        int which = n >> 10, c = n & 1023, hh = c >> 6, dd = c & 63;
                        float* dst = (which == 0) ? g_Q : (which == 1) ? g_K : g_V;
                        dst[(((size_t)bb * 16 + hh) * 2048 + tt) * 64 + dd] = v;
                    } else {
                        Out[(size_t)m * 1024 + n] = v;
                    }
                }
            }
        }
    }
}

// ---------------------------------------------------------------------------
// Flash attention, 3xBF16 split. Block = 128 threads (4 warps), 64 q-rows.
// Smem planes (bf16, stride 72 -> word stride 36 == 4 mod 32, conflict-free):
//   Qh/Ql [q][k], Kh/Kl [n=key][k], Vh/Vl [n=d][k] (transposed), Ph/Pl [q][k]
// ---------------------------------------------------------------------------
#define AS 72
#define PLANE (64 * AS)

__global__ void __launch_bounds__(128) attn_bf16()
{
    extern __shared__ bf16 smb[];
    bf16* Qh = smb;             bf16* Ql = Qh + PLANE;
    bf16* Kh = Ql + PLANE;      bf16* Kl = Kh + PLANE;
    bf16* Vh = Kl + PLANE;      bf16* Vl = Vh + PLANE;
    bf16* Ph = Vl + PLANE;      bf16* Pl = Ph + PLANE;

    const int tid = threadIdx.x;
    const int qt = blockIdx.x, bh = blockIdx.y;
    const float* Qg = g_Q + (size_t)bh * 2048 * 64;
    const float* Kg = g_K + (size_t)bh * 2048 * 64;
    const float* Vg = g_V + (size_t)bh * 2048 * 64;

    const int warp = tid >> 5, lane = tid & 31;
    const int g = lane >> 2, tq = lane & 3;
    const int qrow0 = warp * 16 + g;

    // load + split Q tile [64][64]
#pragma unroll
    for (int t = 0; t < 8; t++) {
        int lf = tid + t * 128, q = lf >> 4, d4 = (lf & 15) * 4;
        split4(&Qh[q * AS + d4], &Ql[q * AS + d4],
               *(const float4*)(Qg + (size_t)(qt * 64 + q) * 64 + d4));
    }

    float ofrag[8][4];
#pragma unroll
    for (int nt = 0; nt < 8; nt++)
#pragma unroll
        for (int r = 0; r < 4; r++) ofrag[nt][r] = 0.f;
    float mrow[2] = {-INFINITY, -INFINITY}, lrow[2] = {0.f, 0.f};

    for (int kt = 0; kt <= qt; kt++) {
        __syncthreads();  // K/V planes safe to overwrite (orders Q load at kt=0)
#pragma unroll
        for (int t = 0; t < 8; t++) {
            int lf = tid + t * 128, kk = lf >> 4, d4 = (lf & 15) * 4;
            split4(&Kh[kk * AS + d4], &Kl[kk * AS + d4],
                   *(const float4*)(Kg + (size_t)(kt * 64 + kk) * 64 + d4));
            // V transposed: Vs[d][kk]
            float4 vv = *(const float4*)(Vg + (size_t)(kt * 64 + kk) * 64 + d4);
            float vsx[4] = {vv.x, vv.y, vv.z, vv.w};
#pragma unroll
            for (int i = 0; i < 4; i++) {
                bf16 h, l;
                bfsplit(vsx[i], h, l);
                Vh[(d4 + i) * AS + kk] = h;
                Vl[(d4 + i) * AS + kk] = l;
            }
        }
        __syncthreads();

        // S = Q K^T  (m16 x n64 x k64 per warp)
        float sfrag[8][4];
#pragma unroll
        for (int nt = 0; nt < 8; nt++)
#pragma unroll
            for (int r = 0; r < 4; r++) sfrag[nt][r] = 0.f;

#pragma unroll
        for (int k16 = 0; k16 < 4; k16++) {
            int kb = k16 * 16;
            uint32_t ah[4], al[4];
            ah[0] = *(const uint32_t*)&Qh[qrow0 * AS + kb + 2 * tq];
            ah[1] = *(const uint32_t*)&Qh[(qrow0 + 8) * AS + kb + 2 * tq];
            ah[2] = *(const uint32_t*)&Qh[qrow0 * AS + kb + 2 * tq + 8];
            ah[3] = *(const uint32_t*)&Qh[(qrow0 + 8) * AS + kb + 2 * tq + 8];
            al[0] = *(const uint32_t*)&Ql[qrow0 * AS + kb + 2 * tq];
            al[1] = *(const uint32_t*)&Ql[(qrow0 + 8) * AS + kb + 2 * tq];
            al[2] = *(const uint32_t*)&Ql[qrow0 * AS + kb + 2 * tq + 8];
            al[3] = *(const uint32_t*)&Ql[(qrow0 + 8) * AS + kb + 2 * tq + 8];
#pragma unroll
            for (int nt = 0; nt < 8; nt++) {
                int nr = nt * 8 + g;
                uint32_t bh2[2], bl2[2];
                bh2[0] = *(const uint32_t*)&Kh[nr * AS + kb + 2 * tq];
                bh2[1] = *(const uint32_t*)&Kh[nr * AS + kb + 2 * tq + 8];
                bl2[0] = *(const uint32_t*)&Kl[nr * AS + kb + 2 * tq];
                bl2[1] = *(const uint32_t*)&Kl[nr * AS + kb + 2 * tq + 8];
                mma16(sfrag[nt], ah, bh2);
                mma16(sfrag[nt], al, bh2);
                mma16(sfrag[nt], ah, bl2);
            }
        }

        // softmax on fragments
        const bool diag = (kt == qt);
#pragma unroll
        for (int r = 0; r < 2; r++) {
            int lq = qrow0 + r * 8;
            float rm = -INFINITY;
#pragma unroll
            for (int nt = 0; nt < 8; nt++) {
#pragma unroll
                for (int cc = 0; cc < 2; cc++) {
                    float sv = sfrag[nt][r * 2 + cc] * 0.125f;  // 1/sqrt(64)
                    int lk = nt * 8 + tq * 2 + cc;
                    if (diag && lk > lq) sv = -INFINITY;
                    sfrag[nt][r * 2 + cc] = sv;
                    rm = fmaxf(rm, sv);
                }
            }
            rm = fmaxf(rm, __shfl_xor_sync(0xffffffffu, rm, 1));
            rm = fmaxf(rm, __shfl_xor_sync(0xffffffffu, rm, 2));
            float mnew = fmaxf(mrow[r], rm);
            float esc = __expf(mrow[r] - mnew);
            float rs = 0.f;
#pragma unroll
            for (int nt = 0; nt < 8; nt++) {
                float p0 = __expf(sfrag[nt][r * 2] - mnew);
                float p1 = __expf(sfrag[nt][r * 2 + 1] - mnew);
                float l0, l1;
                uint32_t hw = packbf2(p0, p1, l0, l1);
                union { bf16 h[2]; uint32_t u; } lw;
                lw.h[0] = __float2bfloat16(l0);
                lw.h[1] = __float2bfloat16(l1);
                int off = lq * AS + nt * 8 + tq * 2;
                *(uint32_t*)&Ph[off] = hw;
                *(uint32_t*)&Pl[off] = lw.u;
                rs += p0 + p1;
            }
            rs += __shfl_xor_sync(0xffffffffu, rs, 1);
            rs += __shfl_xor_sync(0xffffffffu, rs, 2);
            lrow[r] = lrow[r] * esc + rs;
            mrow[r] = mnew;
#pragma unroll
            for (int nt = 0; nt < 8; nt++) {
                ofrag[nt][r * 2] *= esc;
                ofrag[nt][r * 2 + 1] *= esc;
            }
        }
        __syncwarp();  // P rows are warp-private

        // O += P V  (m16 x n64 x k64)
#pragma unroll
        for (int k16 = 0; k16 < 4; k16++) {
            int kb = k16 * 16;
            uint32_t ah[4], al[4];
            ah[0] = *(const uint32_t*)&Ph[qrow0 * AS + kb + 2 * tq];
            ah[1] = *(const uint32_t*)&Ph[(qrow0 + 8) * AS + kb + 2 * tq];
            ah[2] = *(const uint32_t*)&Ph[qrow0 * AS + kb + 2 * tq + 8];
            ah[3] = *(const uint32_t*)&Ph[(qrow0 + 8) * AS + kb + 2 * tq + 8];
            al[0] = *(const uint32_t*)&Pl[qrow0 * AS + kb + 2 * tq];
            al[1] = *(const uint32_t*)&Pl[(qrow0 + 8) * AS + kb + 2 * tq];
            al[2] = *(const uint32_t*)&Pl[qrow0 * AS + kb + 2 * tq + 8];
            al[3] = *(const uint32_t*)&Pl[(qrow0 + 8) * AS + kb + 2 * tq + 8];
#pragma unroll
            for (int nt = 0; nt < 8; nt++) {
                int nr = nt * 8 + g;  // d-row of transposed V
                uint32_t bh2[2], bl2[2];
                bh2[0] = *(const uint32_t*)&Vh[nr * AS + kb + 2 * tq];
                bh2[1] = *(const uint32_t*)&Vh[nr * AS + kb + 2 * tq + 8];
                bl2[0] = *(const uint32_t*)&Vl[nr * AS + kb + 2 * tq];
                bl2[1] = *(const uint32_t*)&Vl[nr * AS + kb + 2 * tq + 8];
                mma16(ofrag[nt], ah, bh2);
                mma16(ofrag[nt], al, bh2);
                mma16(ofrag[nt], ah, bl2);
            }
        }
    }

    // normalize + write [B,T,C]
    const int b = bh >> 4, h = bh & 15;
#pragma unroll
    for (int r = 0; r < 2; r++) {
        float inv = 1.f / lrow[r];
        int q = qt * 64 + qrow0 + r * 8;
#pragma unroll
        for (int nt = 0; nt < 8; nt++) {
            float2 v = make_float2(ofrag[nt][r * 2] * inv, ofrag[nt][r * 2 + 1] * inv);
            *(float2*)&g_O[((size_t)b * 2048 + q) * 1024 + h * 64 + nt * 8 + tq * 2] = v;
        }
    }
}

// ---------------------------------------------------------------------------
extern "C" void kernel_launch(void* const* d_in, const int* in_sizes, int n_in,
                              void* d_out, int out_size)
{
    const float* x     = (const float*)d_in[0];
    const float* qkv_w = (const float*)d_in[1];
    const float* qkv_b = (const float*)d_in[2];
    const float* out_w = (const float*)d_in[3];
    const float* out_b = (const float*)d_in[4];
    float* out = (float*)d_out;

    gemm_bf16<0><<<dim3(24, 32), 256>>>(x, qkv_w, qkv_b, nullptr);

    const int smem_bytes = 8 * PLANE * (int)sizeof(bf16);  // 73,728 B
    cudaFuncSetAttribute(attn_bf16, cudaFuncAttributeMaxDynamicSharedMemorySize, smem_bytes);
    attn_bf16<<<dim3(32, 32), 128, smem_bytes>>>();

    gemm_bf16<1><<<dim3(8, 32), 256>>>(nullptr, out_w, out_b, out);
}

// round 5
// speedup vs baseline: 2.1482x; 1.1421x over previous
#include <cuda_runtime.h>
#include <cuda_bf16.h>
#include <math.h>
#include <stdint.h>

// Problem constants: B=2, T=2048, C=1024, H=16, D=64
__device__ __align__(256) float g_Q[2u * 16 * 2048 * 64];  // [B,H,T,D]
__device__ __align__(256) float g_K[2u * 16 * 2048 * 64];
__device__ __align__(256) float g_V[2u * 16 * 2048 * 64];
__device__ __align__(256) float g_O[4096u * 1024];         // [B,T,C]

typedef __nv_bfloat16 bf16;

// ---------------------------------------------------------------------------
// helpers
// ---------------------------------------------------------------------------
__device__ __forceinline__ void bfsplit(float x, bf16& h, bf16& l) {
    h = __float2bfloat16(x);
    l = __float2bfloat16(x - __bfloat162float(h));
}
__device__ __forceinline__ void split4(bf16* ph, bf16* pl, float4 v) {
    bf16 h[4], l[4];
    bfsplit(v.x, h[0], l[0]); bfsplit(v.y, h[1], l[1]);
    bfsplit(v.z, h[2], l[2]); bfsplit(v.w, h[3], l[3]);
    *(uint2*)ph = *(const uint2*)h;
    *(uint2*)pl = *(const uint2*)l;
}
// D += A*B  (m16n8k16, bf16 inputs, fp32 accum)
__device__ __forceinline__ void mma16(float* d, const uint32_t* a, const uint32_t* b) {
    asm volatile(
        "mma.sync.aligned.m16n8k16.row.col.f32.bf16.bf16.f32 "
        "{%0,%1,%2,%3},{%4,%5,%6,%7},{%8,%9},{%0,%1,%2,%3};"
        : "+f"(d[0]), "+f"(d[1]), "+f"(d[2]), "+f"(d[3])
        : "r"(a[0]), "r"(a[1]), "r"(a[2]), "r"(a[3]), "r"(b[0]), "r"(b[1]));
}

// ---------------------------------------------------------------------------
// 3xBF16-split GEMM: out[m][n] = sum_k A[m,k]*Wt[n,k] + bias[n]
// Block 128x128, BK=16, 8 warps (2m x 4n), warp tile 64x32.
// Single __syncthreads per k-iter: store stage kt+1 (held in regs) into buf^1
// while computing buf; LDG stage kt+2. Prefetch distance 2.
// ---------------------------------------------------------------------------
#define GS 24  // bf16 row stride: word stride 12 -> conflict-free frag reads

template <int MODE>
__global__ void __launch_bounds__(256, 1) gemm_bf16(const float* __restrict__ Aext,
                                                    const float* __restrict__ Wt,
                                                    const float* __restrict__ bias,
                                                    float* __restrict__ Out)
{
    const float* A = (MODE == 0) ? Aext : g_O;
    __shared__ bf16 Ah[2][128][GS], Al[2][128][GS];
    __shared__ bf16 Bh[2][128][GS], Bl[2][128][GS];  // 48KB

    const int tid = threadIdx.x;
    const int m0 = blockIdx.y * 128, n0 = blockIdx.x * 128;
    const int warp = tid >> 5, lane = tid & 31;
    const int wm = (warp >> 2) * 64, wn = (warp & 3) * 32;
    const int g = lane >> 2, tq = lane & 3;

    const int row_a = tid >> 2;               // loader row (stage copy)
    const int c4 = (tid & 3) * 4;             // loader col-4
    const float* gA = A + (size_t)(m0 + row_a) * 1024 + c4;
    const float* gB = Wt + (size_t)(n0 + row_a) * 1024 + c4;
    const float* gA2 = A + (size_t)(m0 + row_a + 64) * 1024 + c4;
    const float* gB2 = Wt + (size_t)(n0 + row_a + 64) * 1024 + c4;

    float acc[4][4][4];
#pragma unroll
    for (int mt = 0; mt < 4; mt++)
#pragma unroll
        for (int nt = 0; nt < 4; nt++)
#pragma unroll
            for (int r = 0; r < 4; r++) acc[mt][nt][r] = 0.f;

    float4 ra[2], rb[2];
    // stage 0 -> buf0
    ra[0] = *(const float4*)gA;  ra[1] = *(const float4*)gA2;
    rb[0] = *(const float4*)gB;  rb[1] = *(const float4*)gB2;
    split4(&Ah[0][row_a][c4], &Al[0][row_a][c4], ra[0]);
    split4(&Ah[0][row_a + 64][c4], &Al[0][row_a + 64][c4], ra[1]);
    split4(&Bh[0][row_a][c4], &Bl[0][row_a][c4], rb[0]);
    split4(&Bh[0][row_a + 64][c4], &Bl[0][row_a + 64][c4], rb[1]);
    // stage 1 -> regs
    ra[0] = *(const float4*)(gA + 16);  ra[1] = *(const float4*)(gA2 + 16);
    rb[0] = *(const float4*)(gB + 16);  rb[1] = *(const float4*)(gB2 + 16);
    __syncthreads();

    for (int kt = 0; kt < 64; kt++) {
        const int buf = kt & 1;
        // store stage kt+1 (in regs) into buf^1; its prior readers finished
        // before the barrier that ended iter kt-1.
        if (kt < 63) {
            split4(&Ah[buf ^ 1][row_a][c4], &Al[buf ^ 1][row_a][c4], ra[0]);
            split4(&Ah[buf ^ 1][row_a + 64][c4], &Al[buf ^ 1][row_a + 64][c4], ra[1]);
            split4(&Bh[buf ^ 1][row_a][c4], &Bl[buf ^ 1][row_a][c4], rb[0]);
            split4(&Bh[buf ^ 1][row_a + 64][c4], &Bl[buf ^ 1][row_a + 64][c4], rb[1]);
        }
        if (kt < 62) {
            int k0 = (kt + 2) * 16;
            ra[0] = *(const float4*)(gA + k0);  ra[1] = *(const float4*)(gA2 + k0);
            rb[0] = *(const float4*)(gB + k0);  rb[1] = *(const float4*)(gB2 + k0);
        }
        // fragments (single b32 each) + mma
        uint32_t Ahf[4][4], Alf[4][4];
#pragma unroll
        for (int mt = 0; mt < 4; mt++) {
            int r0 = wm + mt * 16 + g;
            Ahf[mt][0] = *(const uint32_t*)&Ah[buf][r0][2 * tq];
            Ahf[mt][1] = *(const uint32_t*)&Ah[buf][r0 + 8][2 * tq];
            Ahf[mt][2] = *(const uint32_t*)&Ah[buf][r0][2 * tq + 8];
            Ahf[mt][3] = *(const uint32_t*)&Ah[buf][r0 + 8][2 * tq + 8];
            Alf[mt][0] = *(const uint32_t*)&Al[buf][r0][2 * tq];
            Alf[mt][1] = *(const uint32_t*)&Al[buf][r0 + 8][2 * tq];
            Alf[mt][2] = *(const uint32_t*)&Al[buf][r0][2 * tq + 8];
            Alf[mt][3] = *(const uint32_t*)&Al[buf][r0 + 8][2 * tq + 8];
        }
        uint32_t Bhf[4][2], Blf[4][2];
#pragma unroll
        for (int nt = 0; nt < 4; nt++) {
            int c0r = wn + nt * 8 + g;
            Bhf[nt][0] = *(const uint32_t*)&Bh[buf][c0r][2 * tq];
            Bhf[nt][1] = *(const uint32_t*)&Bh[buf][c0r][2 * tq + 8];
            Blf[nt][0] = *(const uint32_t*)&Bl[buf][c0r][2 * tq];
            Blf[nt][1] = *(const uint32_t*)&Bl[buf][c0r][2 * tq + 8];
        }
#pragma unroll
        for (int mt = 0; mt < 4; mt++)
#pragma unroll
            for (int nt = 0; nt < 4; nt++) {
                mma16(acc[mt][nt], Ahf[mt], Bhf[nt]);
                mma16(acc[mt][nt], Alf[mt], Bhf[nt]);
                mma16(acc[mt][nt], Ahf[mt], Blf[nt]);
            }
        if (kt < 63) __syncthreads();
    }

    // epilogue
#pragma unroll
    for (int mt = 0; mt < 4; mt++) {
#pragma unroll
        for (int rr = 0; rr < 2; rr++) {
            int m = m0 + wm + mt * 16 + g + rr * 8;
#pragma unroll
            for (int nt = 0; nt < 4; nt++) {
#pragma unroll
                for (int cc = 0; cc < 2; cc++) {
                    int n = n0 + wn + nt * 8 + tq * 2 + cc;
                    float v = acc[mt][nt][rr * 2 + cc] + bias[n];
                    if (MODE == 0) {
                        int bb = m >> 11, tt = m & 2047;
                        int which = n >> 10, c = n & 1023, hh = c >> 6, dd = c & 63;
                        float* dst = (which == 0) ? g_Q : (which == 1) ? g_K : g_V;
                        dst[(((size_t)bb * 16 + hh) * 2048 + tt) * 64 + dd] = v;
                    } else {
                        Out[(size_t)m * 1024 + n] = v;
                    }
                }
            }
        }
    }
}

// ---------------------------------------------------------------------------
// Flash attention, 3xBF16 split. Block = 256 threads (8 warps), 128 q-rows,
// sharing each 64-key K/V tile. Warp w owns q-rows [16w,16w+16) (local).
// Causal: per-warp full skip, global-index masking near the diagonal.
// ---------------------------------------------------------------------------
#define AS 72                 // bf16 stride: word stride 36 == 4 mod 32
#define KPLANE (64 * AS)
#define QPLANE (128 * AS)

__global__ void __launch_bounds__(256) attn_bf16()
{
    extern __shared__ bf16 smb[];
    bf16* Qh = smb;              bf16* Ql = Qh + QPLANE;   // [128][AS]
    bf16* Kh = Ql + QPLANE;      bf16* Kl = Kh + KPLANE;   // [64][AS]
    bf16* Vh = Kl + KPLANE;      bf16* Vl = Vh + KPLANE;   // [64][AS] (transposed [d][kk])
    bf16* Ph = Vl + KPLANE;      bf16* Pl = Ph + QPLANE;   // [128][AS]

    const int tid = threadIdx.x;
    const int qt2 = gridDim.x - 1 - blockIdx.x;  // heavy blocks first
    const int bh = blockIdx.y;
    const int Q0 = qt2 * 128;
    const float* Qg = g_Q + (size_t)bh * 2048 * 64;
    const float* Kg = g_K + (size_t)bh * 2048 * 64;
    const float* Vg = g_V + (size_t)bh * 2048 * 64;

    const int warp = tid >> 5, lane = tid & 31;
    const int g = lane >> 2, tq = lane & 3;
    const int lq0 = warp * 16 + g;       // local q-row (c-frag r=0)
    const int qwmin = Q0 + warp * 16;    // warp's min global q

    // load + split Q tile [128][64]
#pragma unroll
    for (int t = 0; t < 8; t++) {
        int lf = tid + t * 256, q = lf >> 4, d4 = (lf & 15) * 4;
        split4(&Qh[q * AS + d4], &Ql[q * AS + d4],
               *(const float4*)(Qg + (size_t)(Q0 + q) * 64 + d4));
    }

    float ofrag[8][4];
#pragma unroll
    for (int nt = 0; nt < 8; nt++)
#pragma unroll
        for (int r = 0; r < 4; r++) ofrag[nt][r] = 0.f;
    float mrow[2] = {-INFINITY, -INFINITY}, lrow[2] = {0.f, 0.f};

    const int ktmax = 2 * qt2 + 1;
    for (int kt = 0; kt <= ktmax; kt++) {
        __syncthreads();  // K/V planes safe to overwrite (orders Q load at kt=0)
#pragma unroll
        for (int t = 0; t < 4; t++) {
            int lf = tid + t * 256, kk = lf >> 4, d4 = (lf & 15) * 4;
            split4(&Kh[kk * AS + d4], &Kl[kk * AS + d4],
                   *(const float4*)(Kg + (size_t)(kt * 64 + kk) * 64 + d4));
            float4 vv = *(const float4*)(Vg + (size_t)(kt * 64 + kk) * 64 + d4);
            float vsx[4] = {vv.x, vv.y, vv.z, vv.w};
#pragma unroll
            for (int i = 0; i < 4; i++) {
                bf16 h, l;
                bfsplit(vsx[i], h, l);
                Vh[(d4 + i) * AS + kk] = h;
                Vl[(d4 + i) * AS + kk] = l;
            }
        }
        __syncthreads();

        const int k0g = kt * 64;
        if (k0g > qwmin + 15) continue;          // tile entirely above diagonal for this warp
        const bool needmask = (k0g + 63 > qwmin);

        // S = Q K^T  (m16 x n64 x k64 per warp)
        float sfrag[8][4];
#pragma unroll
        for (int nt = 0; nt < 8; nt++)
#pragma unroll
            for (int r = 0; r < 4; r++) sfrag[nt][r] = 0.f;

#pragma unroll
        for (int k16 = 0; k16 < 4; k16++) {
            int kb = k16 * 16;
            uint32_t ah[4], al[4];
            ah[0] = *(const uint32_t*)&Qh[lq0 * AS + kb + 2 * tq];
            ah[1] = *(const uint32_t*)&Qh[(lq0 + 8) * AS + kb + 2 * tq];
            ah[2] = *(const uint32_t*)&Qh[lq0 * AS + kb + 2 * tq + 8];
            ah[3] = *(const uint32_t*)&Qh[(lq0 + 8) * AS + kb + 2 * tq + 8];
            al[0] = *(const uint32_t*)&Ql[lq0 * AS + kb + 2 * tq];
            al[1] = *(const uint32_t*)&Ql[(lq0 + 8) * AS + kb + 2 * tq];
            al[2] = *(const uint32_t*)&Ql[lq0 * AS + kb + 2 * tq + 8];
            al[3] = *(const uint32_t*)&Ql[(lq0 + 8) * AS + kb + 2 * tq + 8];
#pragma unroll
            for (int nt = 0; nt < 8; nt++) {
                int nr = nt * 8 + g;
                uint32_t bh2[2], bl2[2];
                bh2[0] = *(const uint32_t*)&Kh[nr * AS + kb + 2 * tq];
                bh2[1] = *(const uint32_t*)&Kh[nr * AS + kb + 2 * tq + 8];
                bl2[0] = *(const uint32_t*)&Kl[nr * AS + kb + 2 * tq];
                bl2[1] = *(const uint32_t*)&Kl[nr * AS + kb + 2 * tq + 8];
                mma16(sfrag[nt], ah, bh2);
                mma16(sfrag[nt], al, bh2);
                mma16(sfrag[nt], ah, bl2);
            }
        }

        // softmax on fragments
#pragma unroll
        for (int r = 0; r < 2; r++) {
            int lq = lq0 + r * 8;
            int qglob = Q0 + lq;
            float rm = -INFINITY;
#pragma unroll
            for (int nt = 0; nt < 8; nt++) {
#pragma unroll
                for (int cc = 0; cc < 2; cc++) {
                    float sv = sfrag[nt][r * 2 + cc] * 0.125f;  // 1/sqrt(64)
                    int keyg = k0g + nt * 8 + tq * 2 + cc;
                    if (needmask && keyg > qglob) sv = -INFINITY;
                    sfrag[nt][r * 2 + cc] = sv;
                    rm = fmaxf(rm, sv);
                }
            }
            rm = fmaxf(rm, __shfl_xor_sync(0xffffffffu, rm, 1));
            rm = fmaxf(rm, __shfl_xor_sync(0xffffffffu, rm, 2));
            float mnew = fmaxf(mrow[r], rm);
            float esc = __expf(mrow[r] - mnew);
            float rs = 0.f;
#pragma unroll
            for (int nt = 0; nt < 8; nt++) {
                float p0 = __expf(sfrag[nt][r * 2] - mnew);
                float p1 = __expf(sfrag[nt][r * 2 + 1] - mnew);
                union { bf16 h[2]; uint32_t u; } hw, lw;
                hw.h[0] = __float2bfloat16(p0);
                hw.h[1] = __float2bfloat16(p1);
                lw.h[0] = __float2bfloat16(p0 - __bfloat162float(hw.h[0]));
                lw.h[1] = __float2bfloat16(p1 - __bfloat162float(hw.h[1]));
                int off = lq * AS + nt * 8 + tq * 2;
                *(uint32_t*)&Ph[off] = hw.u;
                *(uint32_t*)&Pl[off] = lw.u;
                rs += p0 + p1;
            }
            rs += __shfl_xor_sync(0xffffffffu, rs, 1);
            rs += __shfl_xor_sync(0xffffffffu, rs, 2);
            lrow[r] = lrow[r] * esc + rs;
            mrow[r] = mnew;
#pragma unroll
            for (int nt = 0; nt < 8; nt++) {
                ofrag[nt][r * 2] *= esc;
                ofrag[nt][r * 2 + 1] *= esc;
            }
        }
        __syncwarp();  // P rows are warp-private

        // O += P V
#pragma unroll
        for (int k16 = 0; k16 < 4; k16++) {
            int kb = k16 * 16;
            uint32_t ah[4], al[4];
            ah[0] = *(const uint32_t*)&Ph[lq0 * AS + kb + 2 * tq];
            ah[1] = *(const uint32_t*)&Ph[(lq0 + 8) * AS + kb + 2 * tq];
            ah[2] = *(const uint32_t*)&Ph[lq0 * AS + kb + 2 * tq + 8];
            ah[3] = *(const uint32_t*)&Ph[(lq0 + 8) * AS + kb + 2 * tq + 8];
            al[0] = *(const uint32_t*)&Pl[lq0 * AS + kb + 2 * tq];
            al[1] = *(const uint32_t*)&Pl[(lq0 + 8) * AS + kb + 2 * tq];
            al[2] = *(const uint32_t*)&Pl[lq0 * AS + kb + 2 * tq + 8];
            al[3] = *(const uint32_t*)&Pl[(lq0 + 8) * AS + kb + 2 * tq + 8];
#pragma unroll
            for (int nt = 0; nt < 8; nt++) {
                int nr = nt * 8 + g;  // d-row of transposed V
                uint32_t bh2[2], bl2[2];
                bh2[0] = *(const uint32_t*)&Vh[nr * AS + kb + 2 * tq];
                bh2[1] = *(const uint32_t*)&Vh[nr * AS + kb + 2 * tq + 8];
                bl2[0] = *(const uint32_t*)&Vl[nr * AS + kb + 2 * tq];
                bl2[1] = *(const uint32_t*)&Vl[nr * AS + kb + 2 * tq + 8];
                mma16(ofrag[nt], ah, bh2);
                mma16(ofrag[nt], al, bh2);
                mma16(ofrag[nt], ah, bl2);
            }
        }
    }

    // normalize + write [B,T,C]
    const int b = bh >> 4, h = bh & 15;
#pragma unroll
    for (int r = 0; r < 2; r++) {
        float inv = 1.f / lrow[r];
        int q = Q0 + lq0 + r * 8;
#pragma unroll
        for (int nt = 0; nt < 8; nt++) {
            float2 v = make_float2(ofrag[nt][r * 2] * inv, ofrag[nt][r * 2 + 1] * inv);
            *(float2*)&g_O[((size_t)b * 2048 + q) * 1024 + h * 64 + nt * 8 + tq * 2] = v;
        }
    }
}

// ---------------------------------------------------------------------------
extern "C" void kernel_launch(void* const* d_in, const int* in_sizes, int n_in,
                              void* d_out, int out_size)
{
    const float* x     = (const float*)d_in[0];
    const float* qkv_w = (const float*)d_in[1];
    const float* qkv_b = (const float*)d_in[2];
    const float* out_w = (const float*)d_in[3];
    const float* out_b = (const float*)d_in[4];
    float* out = (float*)d_out;

    gemm_bf16<0><<<dim3(24, 32), 256>>>(x, qkv_w, qkv_b, nullptr);

    const int smem_bytes = (4 * QPLANE + 4 * KPLANE) * (int)sizeof(bf16);  // 110,592 B
    cudaFuncSetAttribute(attn_bf16, cudaFuncAttributeMaxDynamicSharedMemorySize, smem_bytes);
    attn_bf16<<<dim3(16, 32), 256, smem_bytes>>>();

    gemm_bf16<1><<<dim3(8, 32), 256>>>(nullptr, out_w, out_b, out);
}

// round 7
// speedup vs baseline: 2.1973x; 1.0229x over previous
#include <cuda_runtime.h>
#include <cuda_bf16.h>
#include <math.h>
#include <stdint.h>

// Problem constants: B=2, T=2048, C=1024, H=16, D=64
__device__ __align__(256) float g_Q[2u * 16 * 2048 * 64];  // [B,H,T,D]
__device__ __align__(256) float g_K[2u * 16 * 2048 * 64];
__device__ __align__(256) float g_V[2u * 16 * 2048 * 64];
__device__ __align__(256) float g_O[4096u * 1024];         // [B,T,C]

typedef __nv_bfloat16 bf16;

// ---------------------------------------------------------------------------
// helpers
// ---------------------------------------------------------------------------
__device__ __forceinline__ void bfsplit(float x, bf16& h, bf16& l) {
    h = __float2bfloat16(x);
    l = __float2bfloat16(x - __bfloat162float(h));
}
__device__ __forceinline__ void split4(bf16* ph, bf16* pl, float4 v) {
    bf16 h[4], l[4];
    bfsplit(v.x, h[0], l[0]); bfsplit(v.y, h[1], l[1]);
    bfsplit(v.z, h[2], l[2]); bfsplit(v.w, h[3], l[3]);
    *(uint2*)ph = *(const uint2*)h;
    *(uint2*)pl = *(const uint2*)l;
}
// D += A*B  (m16n8k16, bf16 inputs, fp32 accum)
__device__ __forceinline__ void mma16(float* d, const uint32_t* a, const uint32_t* b) {
    asm volatile(
        "mma.sync.aligned.m16n8k16.row.col.f32.bf16.bf16.f32 "
        "{%0,%1,%2,%3},{%4,%5,%6,%7},{%8,%9},{%0,%1,%2,%3};"
        : "+f"(d[0]), "+f"(d[1]), "+f"(d[2]), "+f"(d[3])
        : "r"(a[0]), "r"(a[1]), "r"(a[2]), "r"(a[3]), "r"(b[0]), "r"(b[1]));
}

// ---------------------------------------------------------------------------
// 3xBF16-split GEMM: out[m][n] = sum_k A[m,k]*Wt[n,k] + bias[n]
// Block 128x128, BK=16, 16 warps (4m x 4n), warp tile 32x32, 512 threads.
// Single __syncthreads per k-iter: store stage kt+1 (in regs) into buf^1
// while computing buf; LDG stage kt+2. Prefetch distance 2.
// ---------------------------------------------------------------------------
#define GS 24  // bf16 row stride: word stride 12 -> conflict-free frag reads

template <int MODE>
__global__ void __launch_bounds__(512, 1) gemm_bf16(const float* __restrict__ Aext,
                                                    const float* __restrict__ Wt,
                                                    const float* __restrict__ bias,
                                                    float* __restrict__ Out)
{
    const float* A = (MODE == 0) ? Aext : g_O;
    __shared__ bf16 Ah[2][128][GS], Al[2][128][GS];
    __shared__ bf16 Bh[2][128][GS], Bl[2][128][GS];  // 48KB

    const int tid = threadIdx.x;
    const int m0 = blockIdx.y * 128, n0 = blockIdx.x * 128;
    const int warp = tid >> 5, lane = tid & 31;
    const int wm = (warp >> 2) * 32, wn = (warp & 3) * 32;
    const int g = lane >> 2, tq = lane & 3;

    const int row_a = tid >> 2;               // loader row (0..127)
    const int c4 = (tid & 3) * 4;             // loader col-4 (0,4,8,12)
    const float* gA = A + (size_t)(m0 + row_a) * 1024 + c4;
    const float* gB = Wt + (size_t)(n0 + row_a) * 1024 + c4;

    float acc[2][4][4];
#pragma unroll
    for (int mt = 0; mt < 2; mt++)
#pragma unroll
        for (int nt = 0; nt < 4; nt++)
#pragma unroll
            for (int r = 0; r < 4; r++) acc[mt][nt][r] = 0.f;

    float4 ra, rb;
    // stage 0 -> buf0
    ra = *(const float4*)gA;
    rb = *(const float4*)gB;
    split4(&Ah[0][row_a][c4], &Al[0][row_a][c4], ra);
    split4(&Bh[0][row_a][c4], &Bl[0][row_a][c4], rb);
    // stage 1 -> regs
    ra = *(const float4*)(gA + 16);
    rb = *(const float4*)(gB + 16);
    __syncthreads();

    for (int kt = 0; kt < 64; kt++) {
        const int buf = kt & 1;
        // store stage kt+1 (in regs) into buf^1
        if (kt < 63) {
            split4(&Ah[buf ^ 1][row_a][c4], &Al[buf ^ 1][row_a][c4], ra);
            split4(&Bh[buf ^ 1][row_a][c4], &Bl[buf ^ 1][row_a][c4], rb);
        }
        if (kt < 62) {
            int k0 = (kt + 2) * 16;
            ra = *(const float4*)(gA + k0);
            rb = *(const float4*)(gB + k0);
        }
        // fragments (single b32 each) + mma
        uint32_t Ahf[2][4], Alf[2][4];
#pragma unroll
        for (int mt = 0; mt < 2; mt++) {
            int r0 = wm + mt * 16 + g;
            Ahf[mt][0] = *(const uint32_t*)&Ah[buf][r0][2 * tq];
            Ahf[mt][1] = *(const uint32_t*)&Ah[buf][r0 + 8][2 * tq];
            Ahf[mt][2] = *(const uint32_t*)&Ah[buf][r0][2 * tq + 8];
            Ahf[mt][3] = *(const uint32_t*)&Ah[buf][r0 + 8][2 * tq + 8];
            Alf[mt][0] = *(const uint32_t*)&Al[buf][r0][2 * tq];
            Alf[mt][1] = *(const uint32_t*)&Al[buf][r0 + 8][2 * tq];
            Alf[mt][2] = *(const uint32_t*)&Al[buf][r0][2 * tq + 8];
            Alf[mt][3] = *(const uint32_t*)&Al[buf][r0 + 8][2 * tq + 8];
        }
        uint32_t Bhf[4][2], Blf[4][2];
#pragma unroll
        for (int nt = 0; nt < 4; nt++) {
            int c0r = wn + nt * 8 + g;
            Bhf[nt][0] = *(const uint32_t*)&Bh[buf][c0r][2 * tq];
            Bhf[nt][1] = *(const uint32_t*)&Bh[buf][c0r][2 * tq + 8];
            Blf[nt][0] = *(const uint32_t*)&Bl[buf][c0r][2 * tq];
            Blf[nt][1] = *(const uint32_t*)&Bl[buf][c0r][2 * tq + 8];
        }
#pragma unroll
        for (int mt = 0; mt < 2; mt++)
#pragma unroll
            for (int nt = 0; nt < 4; nt++) {
                mma16(acc[mt][nt], Ahf[mt], Bhf[nt]);
                mma16(acc[mt][nt], Alf[mt], Bhf[nt]);
                mma16(acc[mt][nt], Ahf[mt], Blf[nt]);
            }
        if (kt < 63) __syncthreads();
    }

    // epilogue
#pragma unroll
    for (int mt = 0; mt < 2; mt++) {
#pragma unroll
        for (int rr = 0; rr < 2; rr++) {
            int m = m0 + wm + mt * 16 + g + rr * 8;
#pragma unroll
            for (int nt = 0; nt < 4; nt++) {
#pragma unroll
                for (int cc = 0; cc < 2; cc++) {
                    int n = n0 + wn + nt * 8 + tq * 2 + cc;
                    float v = acc[mt][nt][rr * 2 + cc] + bias[n];
                    if (MODE == 0) {
                        int bb = m >> 11, tt = m & 2047;
                        int which = n >> 10, c = n & 1023, hh = c >> 6, dd = c & 63;
                        float* dst = (which == 0) ? g_Q : (which == 1) ? g_K : g_V;
                        dst[(((size_t)bb * 16 + hh) * 2048 + tt) * 64 + dd] = v;
                    } else {
                        Out[(size_t)m * 1024 + n] = v;
                    }
                }
            }
        }
    }
}

// ---------------------------------------------------------------------------
// Flash attention, 3xBF16 split (unchanged from Round 5 / 807us baseline).
// Block = 256 threads (8 warps), 128 q-rows, shared 64-key K/V tiles.
// ---------------------------------------------------------------------------
#define AS 72                 // bf16 stride: word stride 36 == 4 mod 32
#define KPLANE (64 * AS)
#define QPLANE (128 * AS)

__global__ void __launch_bounds__(256) attn_bf16()
{
    extern __shared__ bf16 smb[];
    bf16* Qh = smb;              bf16* Ql = Qh + QPLANE;   // [128][AS]
    bf16* Kh = Ql + QPLANE;      bf16* Kl = Kh + KPLANE;   // [64][AS]
    bf16* Vh = Kl + KPLANE;      bf16* Vl = Vh + KPLANE;   // [64][AS] (transposed [d][kk])
    bf16* Ph = Vl + KPLANE;      bf16* Pl = Ph + QPLANE;   // [128][AS]

    const int tid = threadIdx.x;
    const int qt2 = gridDim.x - 1 - blockIdx.x;  // heavy blocks first
    const int bh = blockIdx.y;
    const int Q0 = qt2 * 128;
    const float* Qg = g_Q + (size_t)bh * 2048 * 64;
    const float* Kg = g_K + (size_t)bh * 2048 * 64;
    const float* Vg = g_V + (size_t)bh * 2048 * 64;

    const int warp = tid >> 5, lane = tid & 31;
    const int g = lane >> 2, tq = lane & 3;
    const int lq0 = warp * 16 + g;       // local q-row (c-frag r=0)
    const int qwmin = Q0 + warp * 16;    // warp's min global q

    // load + split Q tile [128][64]
#pragma unroll
    for (int t = 0; t < 8; t++) {
        int lf = tid + t * 256, q = lf >> 4, d4 = (lf & 15) * 4;
        split4(&Qh[q * AS + d4], &Ql[q * AS + d4],
               *(const float4*)(Qg + (size_t)(Q0 + q) * 64 + d4));
    }

    float ofrag[8][4];
#pragma unroll
    for (int nt = 0; nt < 8; nt++)
#pragma unroll
        for (int r = 0; r < 4; r++) ofrag[nt][r] = 0.f;
    float mrow[2] = {-INFINITY, -INFINITY}, lrow[2] = {0.f, 0.f};

    const int ktmax = 2 * qt2 + 1;
    for (int kt = 0; kt <= ktmax; kt++) {
        __syncthreads();  // K/V planes safe to overwrite (orders Q load at kt=0)
#pragma unroll
        for (int t = 0; t < 4; t++) {
            int lf = tid + t * 256, kk = lf >> 4, d4 = (lf & 15) * 4;
            split4(&Kh[kk * AS + d4], &Kl[kk * AS + d4],
                   *(const float4*)(Kg + (size_t)(kt * 64 + kk) * 64 + d4));
            float4 vv = *(const float4*)(Vg + (size_t)(kt * 64 + kk) * 64 + d4);
            float vsx[4] = {vv.x, vv.y, vv.z, vv.w};
#pragma unroll
            for (int i = 0; i < 4; i++) {
                bf16 h, l;
                bfsplit(vsx[i], h, l);
                Vh[(d4 + i) * AS + kk] = h;
                Vl[(d4 + i) * AS + kk] = l;
            }
        }
        __syncthreads();

        const int k0g = kt * 64;
        if (k0g > qwmin + 15) continue;          // tile entirely above diagonal for this warp
        const bool needmask = (k0g + 63 > qwmin);

        // S = Q K^T  (m16 x n64 x k64 per warp)
        float sfrag[8][4];
#pragma unroll
        for (int nt = 0; nt < 8; nt++)
#pragma unroll
            for (int r = 0; r < 4; r++) sfrag[nt][r] = 0.f;

#pragma unroll
        for (int k16 = 0; k16 < 4; k16++) {
            int kb = k16 * 16;
            uint32_t ah[4], al[4];
            ah[0] = *(const uint32_t*)&Qh[lq0 * AS + kb + 2 * tq];
            ah[1] = *(const uint32_t*)&Qh[(lq0 + 8) * AS + kb + 2 * tq];
            ah[2] = *(const uint32_t*)&Qh[lq0 * AS + kb + 2 * tq + 8];
            ah[3] = *(const uint32_t*)&Qh[(lq0 + 8) * AS + kb + 2 * tq + 8];
            al[0] = *(const uint32_t*)&Ql[lq0 * AS + kb + 2 * tq];
            al[1] = *(const uint32_t*)&Ql[(lq0 + 8) * AS + kb + 2 * tq];
            al[2] = *(const uint32_t*)&Ql[lq0 * AS + kb + 2 * tq + 8];
            al[3] = *(const uint32_t*)&Ql[(lq0 + 8) * AS + kb + 2 * tq + 8];
#pragma unroll
            for (int nt = 0; nt < 8; nt++) {
                int nr = nt * 8 + g;
                uint32_t bh2[2], bl2[2];
                bh2[0] = *(const uint32_t*)&Kh[nr * AS + kb + 2 * tq];
                bh2[1] = *(const uint32_t*)&Kh[nr * AS + kb + 2 * tq + 8];
                bl2[0] = *(const uint32_t*)&Kl[nr * AS + kb + 2 * tq];
                bl2[1] = *(const uint32_t*)&Kl[nr * AS + kb + 2 * tq + 8];
                mma16(sfrag[nt], ah, bh2);
                mma16(sfrag[nt], al, bh2);
                mma16(sfrag[nt], ah, bl2);
            }
        }

        // softmax on fragments
#pragma unroll
        for (int r = 0; r < 2; r++) {
            int lq = lq0 + r * 8;
            int qglob = Q0 + lq;
            float rm = -INFINITY;
#pragma unroll
            for (int nt = 0; nt < 8; nt++) {
#pragma unroll
                for (int cc = 0; cc < 2; cc++) {
                    float sv = sfrag[nt][r * 2 + cc] * 0.125f;  // 1/sqrt(64)
                    int keyg = k0g + nt * 8 + tq * 2 + cc;
                    if (needmask && keyg > qglob) sv = -INFINITY;
                    sfrag[nt][r * 2 + cc] = sv;
                    rm = fmaxf(rm, sv);
                }
            }
            rm = fmaxf(rm, __shfl_xor_sync(0xffffffffu, rm, 1));
            rm = fmaxf(rm, __shfl_xor_sync(0xffffffffu, rm, 2));
            float mnew = fmaxf(mrow[r], rm);
            float esc = __expf(mrow[r] - mnew);
            float rs = 0.f;
#pragma unroll
            for (int nt = 0; nt < 8; nt++) {
                float p0 = __expf(sfrag[nt][r * 2] - mnew);
                float p1 = __expf(sfrag[nt][r * 2 + 1] - mnew);
                union { bf16 h[2]; uint32_t u; } hw, lw;
                hw.h[0] = __float2bfloat16(p0);
                hw.h[1] = __float2bfloat16(p1);
                lw.h[0] = __float2bfloat16(p0 - __bfloat162float(hw.h[0]));
                lw.h[1] = __float2bfloat16(p1 - __bfloat162float(hw.h[1]));
                int off = lq * AS + nt * 8 + tq * 2;
                *(uint32_t*)&Ph[off] = hw.u;
                *(uint32_t*)&Pl[off] = lw.u;
                rs += p0 + p1;
            }
            rs += __shfl_xor_sync(0xffffffffu, rs, 1);
            rs += __shfl_xor_sync(0xffffffffu, rs, 2);
            lrow[r] = lrow[r] * esc + rs;
            mrow[r] = mnew;
#pragma unroll
            for (int nt = 0; nt < 8; nt++) {
                ofrag[nt][r * 2] *= esc;
                ofrag[nt][r * 2 + 1] *= esc;
            }
        }
        __syncwarp();  // P rows are warp-private

        // O += P V
#pragma unroll
        for (int k16 = 0; k16 < 4; k16++) {
            int kb = k16 * 16;
            uint32_t ah[4], al[4];
            ah[0] = *(const uint32_t*)&Ph[lq0 * AS + kb + 2 * tq];
            ah[1] = *(const uint32_t*)&Ph[(lq0 + 8) * AS + kb + 2 * tq];
            ah[2] = *(const uint32_t*)&Ph[lq0 * AS + kb + 2 * tq + 8];
            ah[3] = *(const uint32_t*)&Ph[(lq0 + 8) * AS + kb + 2 * tq + 8];
            al[0] = *(const uint32_t*)&Pl[lq0 * AS + kb + 2 * tq];
            al[1] = *(const uint32_t*)&Pl[(lq0 + 8) * AS + kb + 2 * tq];
            al[2] = *(const uint32_t*)&Pl[lq0 * AS + kb + 2 * tq + 8];
            al[3] = *(const uint32_t*)&Pl[(lq0 + 8) * AS + kb + 2 * tq + 8];
#pragma unroll
            for (int nt = 0; nt < 8; nt++) {
                int nr = nt * 8 + g;  // d-row of transposed V
                uint32_t bh2[2], bl2[2];
                bh2[0] = *(const uint32_t*)&Vh[nr * AS + kb + 2 * tq];
                bh2[1] = *(const uint32_t*)&Vh[nr * AS + kb + 2 * tq + 8];
                bl2[0] = *(const uint32_t*)&Vl[nr * AS + kb + 2 * tq];
                bl2[1] = *(const uint32_t*)&Vl[nr * AS + kb + 2 * tq + 8];
                mma16(ofrag[nt], ah, bh2);
                mma16(ofrag[nt], al, bh2);
                mma16(ofrag[nt], ah, bl2);
            }
        }
    }

    // normalize + write [B,T,C]
    const int b = bh >> 4, h = bh & 15;
#pragma unroll
    for (int r = 0; r < 2; r++) {
        float inv = 1.f / lrow[r];
        int q = Q0 + lq0 + r * 8;
#pragma unroll
        for (int nt = 0; nt < 8; nt++) {
            float2 v = make_float2(ofrag[nt][r * 2] * inv, ofrag[nt][r * 2 + 1] * inv);
            *(float2*)&g_O[((size_t)b * 2048 + q) * 1024 + h * 64 + nt * 8 + tq * 2] = v;
        }
    }
}

// ---------------------------------------------------------------------------
extern "C" void kernel_launch(void* const* d_in, const int* in_sizes, int n_in,
                              void* d_out, int out_size)
{
    const float* x     = (const float*)d_in[0];
    const float* qkv_w = (const float*)d_in[1];
    const float* qkv_b = (const float*)d_in[2];
    const float* out_w = (const float*)d_in[3];
    const float* out_b = (const float*)d_in[4];
    float* out = (float*)d_out;

    gemm_bf16<0><<<dim3(24, 32), 512>>>(x, qkv_w, qkv_b, nullptr);

    const int smem_bytes = (4 * QPLANE + 4 * KPLANE) * (int)sizeof(bf16);  // 110,592 B
    cudaFuncSetAttribute(attn_bf16, cudaFuncAttributeMaxDynamicSharedMemorySize, smem_bytes);
    attn_bf16<<<dim3(16, 32), 256, smem_bytes>>>();

    gemm_bf16<1><<<dim3(8, 32), 512>>>(nullptr, out_w, out_b, out);
}

// round 8
// speedup vs baseline: 2.2711x; 1.0336x over previous
#include <cuda_runtime.h>
#include <cuda_bf16.h>
#include <math.h>
#include <stdint.h>

// Problem constants: B=2, T=2048, C=1024, H=16, D=64
__device__ __align__(256) float g_Q[2u * 16 * 2048 * 64];  // [B,H,T,D]
__device__ __align__(256) float g_K[2u * 16 * 2048 * 64];
__device__ __align__(256) float g_V[2u * 16 * 2048 * 64];
__device__ __align__(256) float g_O[4096u * 1024];         // [B,T,C]

typedef __nv_bfloat16 bf16;

// ---------------------------------------------------------------------------
__device__ __forceinline__ void bfsplit(float x, bf16& h, bf16& l) {
    h = __float2bfloat16(x);
    l = __float2bfloat16(x - __bfloat162float(h));
}
__device__ __forceinline__ void split4(bf16* ph, bf16* pl, float4 v) {
    bf16 h[4], l[4];
    bfsplit(v.x, h[0], l[0]); bfsplit(v.y, h[1], l[1]);
    bfsplit(v.z, h[2], l[2]); bfsplit(v.w, h[3], l[3]);
    *(uint2*)ph = *(const uint2*)h;
    *(uint2*)pl = *(const uint2*)l;
}
// D += A*B  (m16n8k16, bf16 inputs, fp32 accum)
__device__ __forceinline__ void mma16(float* d, const uint32_t* a, const uint32_t* b) {
    asm volatile(
        "mma.sync.aligned.m16n8k16.row.col.f32.bf16.bf16.f32 "
        "{%0,%1,%2,%3},{%4,%5,%6,%7},{%8,%9},{%0,%1,%2,%3};"
        : "+f"(d[0]), "+f"(d[1]), "+f"(d[2]), "+f"(d[3])
        : "r"(a[0]), "r"(a[1]), "r"(a[2]), "r"(a[3]), "r"(b[0]), "r"(b[1]));
}

// ---------------------------------------------------------------------------
// 3xBF16-split GEMM: out[m][n] = sum_k A[m,k]*Wt[n,k] + bias[n]
// Block 128(m) x 256(n), BK=16, 8 warps (2m x 4n), warp tile 64x64.
// Single __syncthreads per k-iter (prefetch distance 2, reg-staged stores).
// ---------------------------------------------------------------------------
#define GS 24  // bf16 row stride: word stride 12 -> conflict-free frag reads
#define A_PL (2 * 128 * GS)   // one A plane (both buffers), bf16 elems
#define B_PL (2 * 256 * GS)
#define GEMM_SMEM ((2 * A_PL + 2 * B_PL) * (int)sizeof(bf16))  // 73,728 B

template <int MODE>
__global__ void __launch_bounds__(256, 1) gemm_bf16(const float* __restrict__ Aext,
                                                    const float* __restrict__ Wt,
                                                    const float* __restrict__ bias,
                                                    float* __restrict__ Out)
{
    const float* A = (MODE == 0) ? Aext : g_O;
    extern __shared__ bf16 gsm[];
    bf16* Ah = gsm;            // [2][128][GS]
    bf16* Al = Ah + A_PL;
    bf16* Bh = Al + A_PL;      // [2][256][GS]
    bf16* Bl = Bh + B_PL;

    const int tid = threadIdx.x;
    const int m0 = blockIdx.y * 128, n0 = blockIdx.x * 256;
    const int warp = tid >> 5, lane = tid & 31;
    const int wm = (warp >> 2) * 64, wn = (warp & 3) * 64;
    const int g = lane >> 2, tq = lane & 3;

    const int rowL = tid >> 2;            // 0..63
    const int c4 = (tid & 3) * 4;
    const float* gA = A + (size_t)(m0 + rowL) * 1024 + c4;   // rows rowL, rowL+64
    const float* gB = Wt + (size_t)(n0 + rowL) * 1024 + c4;  // rows rowL..+192

    float acc[4][8][4];
#pragma unroll
    for (int mt = 0; mt < 4; mt++)
#pragma unroll
        for (int nt = 0; nt < 8; nt++)
#pragma unroll
            for (int r = 0; r < 4; r++) acc[mt][nt][r] = 0.f;

    float4 ra[2], rb[4];
    // stage 0 -> buf0
#pragma unroll
    for (int t = 0; t < 2; t++) ra[t] = *(const float4*)(gA + (size_t)t * 64 * 1024);
#pragma unroll
    for (int t = 0; t < 4; t++) rb[t] = *(const float4*)(gB + (size_t)t * 64 * 1024);
#pragma unroll
    for (int t = 0; t < 2; t++)
        split4(&Ah[(rowL + t * 64) * GS + c4], &Al[(rowL + t * 64) * GS + c4], ra[t]);
#pragma unroll
    for (int t = 0; t < 4; t++)
        split4(&Bh[(rowL + t * 64) * GS + c4], &Bl[(rowL + t * 64) * GS + c4], rb[t]);
    // stage 1 -> regs
#pragma unroll
    for (int t = 0; t < 2; t++) ra[t] = *(const float4*)(gA + (size_t)t * 64 * 1024 + 16);
#pragma unroll
    for (int t = 0; t < 4; t++) rb[t] = *(const float4*)(gB + (size_t)t * 64 * 1024 + 16);
    __syncthreads();

    for (int kt = 0; kt < 64; kt++) {
        const int buf = kt & 1;
        const int abase = (buf ^ 1) * 128 * GS;
        const int bbase = (buf ^ 1) * 256 * GS;
        if (kt < 63) {
#pragma unroll
            for (int t = 0; t < 2; t++)
                split4(&Ah[abase + (rowL + t * 64) * GS + c4],
                       &Al[abase + (rowL + t * 64) * GS + c4], ra[t]);
#pragma unroll
            for (int t = 0; t < 4; t++)
                split4(&Bh[bbase + (rowL + t * 64) * GS + c4],
                       &Bl[bbase + (rowL + t * 64) * GS + c4], rb[t]);
        }
        if (kt < 62) {
            int k0 = (kt + 2) * 16;
#pragma unroll
            for (int t = 0; t < 2; t++) ra[t] = *(const float4*)(gA + (size_t)t * 64 * 1024 + k0);
#pragma unroll
            for (int t = 0; t < 4; t++) rb[t] = *(const float4*)(gB + (size_t)t * 64 * 1024 + k0);
        }
        const int ab = buf * 128 * GS;
        const int bb = buf * 256 * GS;
        // A fragments (hi+lo) for 4 m-tiles
        uint32_t Ahf[4][4], Alf[4][4];
#pragma unroll
        for (int mt = 0; mt < 4; mt++) {
            int r0 = (wm + mt * 16 + g) * GS;
            Ahf[mt][0] = *(const uint32_t*)&Ah[ab + r0 + 2 * tq];
            Ahf[mt][1] = *(const uint32_t*)&Ah[ab + r0 + 8 * GS + 2 * tq];
            Ahf[mt][2] = *(const uint32_t*)&Ah[ab + r0 + 2 * tq + 8];
            Ahf[mt][3] = *(const uint32_t*)&Ah[ab + r0 + 8 * GS + 2 * tq + 8];
            Alf[mt][0] = *(const uint32_t*)&Al[ab + r0 + 2 * tq];
            Alf[mt][1] = *(const uint32_t*)&Al[ab + r0 + 8 * GS + 2 * tq];
            Alf[mt][2] = *(const uint32_t*)&Al[ab + r0 + 2 * tq + 8];
            Alf[mt][3] = *(const uint32_t*)&Al[ab + r0 + 8 * GS + 2 * tq + 8];
        }
        // B fragments in two halves of 4 n-tiles (register cap)
#pragma unroll
        for (int nh = 0; nh < 2; nh++) {
            uint32_t Bhf[4][2], Blf[4][2];
#pragma unroll
            for (int j = 0; j < 4; j++) {
                int c0r = (wn + (nh * 4 + j) * 8 + g) * GS;
                Bhf[j][0] = *(const uint32_t*)&Bh[bb + c0r + 2 * tq];
                Bhf[j][1] = *(const uint32_t*)&Bh[bb + c0r + 2 * tq + 8];
                Blf[j][0] = *(const uint32_t*)&Bl[bb + c0r + 2 * tq];
                Blf[j][1] = *(const uint32_t*)&Bl[bb + c0r + 2 * tq + 8];
            }
#pragma unroll
            for (int mt = 0; mt < 4; mt++)
#pragma unroll
                for (int j = 0; j < 4; j++) {
                    float* d = acc[mt][nh * 4 + j];
                    mma16(d, Ahf[mt], Bhf[j]);
                    mma16(d, Alf[mt], Bhf[j]);
                    mma16(d, Ahf[mt], Blf[j]);
                }
        }
        if (kt < 63) __syncthreads();
    }

    // epilogue
#pragma unroll
    for (int mt = 0; mt < 4; mt++) {
#pragma unroll
        for (int rr = 0; rr < 2; rr++) {
            int m = m0 + wm + mt * 16 + g + rr * 8;
#pragma unroll
            for (int nt = 0; nt < 8; nt++) {
#pragma unroll
                for (int cc = 0; cc < 2; cc++) {
                    int n = n0 + wn + nt * 8 + tq * 2 + cc;
                    float v = acc[mt][nt][rr * 2 + cc] + bias[n];
                    if (MODE == 0) {
                        int bb2 = m >> 11, tt = m & 2047;
                        int which = n >> 10, c = n & 1023, hh = c >> 6, dd = c & 63;
                        float* dst = (which == 0) ? g_Q : (which == 1) ? g_K : g_V;
                        dst[(((size_t)bb2 * 16 + hh) * 2048 + tt) * 64 + dd] = v;
                    } else {
                        Out[(size_t)m * 1024 + n] = v;
                    }
                }
            }
        }
    }
}

// ---------------------------------------------------------------------------
// Flash attention, 3xBF16 split. Block = 256 threads (8 warps), 256 q-rows,
// warp q-tile 32 rows (m32 x n64 S/PV per warp). Shared 64-key K/V tiles.
// ---------------------------------------------------------------------------
#define AS 72                 // bf16 stride: word stride 36 == 4 mod 32
#define KPLANE (64 * AS)
#define QPLANE (256 * AS)
#define ATTN_SMEM ((4 * QPLANE + 4 * KPLANE) * (int)sizeof(bf16))  // 184,320 B

__global__ void __launch_bounds__(256) attn_bf16()
{
    extern __shared__ bf16 smb[];
    bf16* Qh = smb;              bf16* Ql = Qh + QPLANE;   // [256][AS]
    bf16* Kh = Ql + QPLANE;      bf16* Kl = Kh + KPLANE;   // [64][AS]
    bf16* Vh = Kl + KPLANE;      bf16* Vl = Vh + KPLANE;   // [64][AS] ([d][kk])
    bf16* Ph = Vl + KPLANE;      bf16* Pl = Ph + QPLANE;   // [256][AS]

    const int tid = threadIdx.x;
    const int qt = gridDim.x - 1 - blockIdx.x;   // heavy blocks first
    const int bh = blockIdx.y;
    const int Q0 = qt * 256;
    const float* Qg = g_Q + (size_t)bh * 2048 * 64;
    const float* Kg = g_K + (size_t)bh * 2048 * 64;
    const float* Vg = g_V + (size_t)bh * 2048 * 64;

    const int warp = tid >> 5, lane = tid & 31;
    const int g = lane >> 2, tq = lane & 3;
    const int lqb = warp * 32;            // warp's local q base
    const int qwmin = Q0 + lqb;

    // load + split Q tile [256][64]
#pragma unroll
    for (int t = 0; t < 16; t++) {
        int lf = tid + t * 256, q = lf >> 4, d4 = (lf & 15) * 4;
        split4(&Qh[q * AS + d4], &Ql[q * AS + d4],
               *(const float4*)(Qg + (size_t)(Q0 + q) * 64 + d4));
    }

    float ofrag[2][8][4];
#pragma unroll
    for (int mt = 0; mt < 2; mt++)
#pragma unroll
        for (int nt = 0; nt < 8; nt++)
#pragma unroll
            for (int r = 0; r < 4; r++) ofrag[mt][nt][r] = 0.f;
    float mrow[2][2], lrow[2][2];
#pragma unroll
    for (int mt = 0; mt < 2; mt++)
#pragma unroll
        for (int r = 0; r < 2; r++) { mrow[mt][r] = -INFINITY; lrow[mt][r] = 0.f; }

    const int ktmax = 4 * qt + 3;
    for (int kt = 0; kt <= ktmax; kt++) {
        __syncthreads();  // K/V planes safe to overwrite (orders Q load at kt=0)
#pragma unroll
        for (int t = 0; t < 4; t++) {
            int lf = tid + t * 256, kk = lf >> 4, d4 = (lf & 15) * 4;
            split4(&Kh[kk * AS + d4], &Kl[kk * AS + d4],
                   *(const float4*)(Kg + (size_t)(kt * 64 + kk) * 64 + d4));
            float4 vv = *(const float4*)(Vg + (size_t)(kt * 64 + kk) * 64 + d4);
            float vsx[4] = {vv.x, vv.y, vv.z, vv.w};
#pragma unroll
            for (int i = 0; i < 4; i++) {
                bf16 h, l;
                bfsplit(vsx[i], h, l);
                Vh[(d4 + i) * AS + kk] = h;
                Vl[(d4 + i) * AS + kk] = l;
            }
        }
        __syncthreads();

        const int k0g = kt * 64;
        if (k0g > qwmin + 31) continue;      // tile fully above diagonal for warp
        const bool needmask = (k0g + 63 > qwmin);

        // S = Q K^T  (m32 x n64 x k64 per warp)
        float sfrag[2][8][4];
#pragma unroll
        for (int mt = 0; mt < 2; mt++)
#pragma unroll
            for (int nt = 0; nt < 8; nt++)
#pragma unroll
                for (int r = 0; r < 4; r++) sfrag[mt][nt][r] = 0.f;

#pragma unroll
        for (int k16 = 0; k16 < 4; k16++) {
            int kb = k16 * 16;
            uint32_t ah[2][4], al[2][4];
#pragma unroll
            for (int mt = 0; mt < 2; mt++) {
                int r0 = (lqb + mt * 16 + g) * AS;
                ah[mt][0] = *(const uint32_t*)&Qh[r0 + kb + 2 * tq];
                ah[mt][1] = *(const uint32_t*)&Qh[r0 + 8 * AS + kb + 2 * tq];
                ah[mt][2] = *(const uint32_t*)&Qh[r0 + kb + 2 * tq + 8];
                ah[mt][3] = *(const uint32_t*)&Qh[r0 + 8 * AS + kb + 2 * tq + 8];
                al[mt][0] = *(const uint32_t*)&Ql[r0 + kb + 2 * tq];
                al[mt][1] = *(const uint32_t*)&Ql[r0 + 8 * AS + kb + 2 * tq];
                al[mt][2] = *(const uint32_t*)&Ql[r0 + kb + 2 * tq + 8];
                al[mt][3] = *(const uint32_t*)&Ql[r0 + 8 * AS + kb + 2 * tq + 8];
            }
#pragma unroll
            for (int nt = 0; nt < 8; nt++) {
                int nr = (nt * 8 + g) * AS;
                uint32_t bh2[2], bl2[2];
                bh2[0] = *(const uint32_t*)&Kh[nr + kb + 2 * tq];
                bh2[1] = *(const uint32_t*)&Kh[nr + kb + 2 * tq + 8];
                bl2[0] = *(const uint32_t*)&Kl[nr + kb + 2 * tq];
                bl2[1] = *(const uint32_t*)&Kl[nr + kb + 2 * tq + 8];
#pragma unroll
                for (int mt = 0; mt < 2; mt++) {
                    mma16(sfrag[mt][nt], ah[mt], bh2);
                    mma16(sfrag[mt][nt], al[mt], bh2);
                    mma16(sfrag[mt][nt], ah[mt], bl2);
                }
            }
        }

        // softmax on fragments
#pragma unroll
        for (int mt = 0; mt < 2; mt++) {
#pragma unroll
            for (int r = 0; r < 2; r++) {
                int lq = lqb + mt * 16 + r * 8 + g;
                int qglob = Q0 + lq;
                float rm = -INFINITY;
#pragma unroll
                for (int nt = 0; nt < 8; nt++) {
#pragma unroll
                    for (int cc = 0; cc < 2; cc++) {
                        float sv = sfrag[mt][nt][r * 2 + cc] * 0.125f;  // 1/sqrt(64)
                        int keyg = k0g + nt * 8 + tq * 2 + cc;
                        if (needmask && keyg > qglob) sv = -INFINITY;
                        sfrag[mt][nt][r * 2 + cc] = sv;
                        rm = fmaxf(rm, sv);
                    }
                }
                rm = fmaxf(rm, __shfl_xor_sync(0xffffffffu, rm, 1));
                rm = fmaxf(rm, __shfl_xor_sync(0xffffffffu, rm, 2));
                float mnew = fmaxf(mrow[mt][r], rm);
                float esc = __expf(mrow[mt][r] - mnew);
                float rs = 0.f;
#pragma unroll
                for (int nt = 0; nt < 8; nt++) {
                    float p0 = __expf(sfrag[mt][nt][r * 2] - mnew);
                    float p1 = __expf(sfrag[mt][nt][r * 2 + 1] - mnew);
                    union { bf16 h[2]; uint32_t u; } hw, lw;
                    hw.h[0] = __float2bfloat16(p0);
                    hw.h[1] = __float2bfloat16(p1);
                    lw.h[0] = __float2bfloat16(p0 - __bfloat162float(hw.h[0]));
                    lw.h[1] = __float2bfloat16(p1 - __bfloat162float(hw.h[1]));
                    int off = lq * AS + nt * 8 + tq * 2;
                    *(uint32_t*)&Ph[off] = hw.u;
                    *(uint32_t*)&Pl[off] = lw.u;
                    rs += p0 + p1;
                }
                rs += __shfl_xor_sync(0xffffffffu, rs, 1);
                rs += __shfl_xor_sync(0xffffffffu, rs, 2);
                lrow[mt][r] = lrow[mt][r] * esc + rs;
                mrow[mt][r] = mnew;
#pragma unroll
                for (int nt = 0; nt < 8; nt++) {
                    ofrag[mt][nt][r * 2] *= esc;
                    ofrag[mt][nt][r * 2 + 1] *= esc;
                }
            }
        }
        __syncwarp();  // P rows are warp-private

        // O += P V  (m32 x n64 x k64)
#pragma unroll
        for (int k16 = 0; k16 < 4; k16++) {
            int kb = k16 * 16;
            uint32_t ah[2][4], al[2][4];
#pragma unroll
            for (int mt = 0; mt < 2; mt++) {
                int r0 = (lqb + mt * 16 + g) * AS;
                ah[mt][0] = *(const uint32_t*)&Ph[r0 + kb + 2 * tq];
                ah[mt][1] = *(const uint32_t*)&Ph[r0 + 8 * AS + kb + 2 * tq];
                ah[mt][2] = *(const uint32_t*)&Ph[r0 + kb + 2 * tq + 8];
                ah[mt][3] = *(const uint32_t*)&Ph[r0 + 8 * AS + kb + 2 * tq + 8];
                al[mt][0] = *(const uint32_t*)&Pl[r0 + kb + 2 * tq];
                al[mt][1] = *(const uint32_t*)&Pl[r0 + 8 * AS + kb + 2 * tq];
                al[mt][2] = *(const uint32_t*)&Pl[r0 + kb + 2 * tq + 8];
                al[mt][3] = *(const uint32_t*)&Pl[r0 + 8 * AS + kb + 2 * tq + 8];
            }
#pragma unroll
            for (int nt = 0; nt < 8; nt++) {
                int nr = (nt * 8 + g) * AS;  // d-row of transposed V
                uint32_t bh2[2], bl2[2];
                bh2[0] = *(const uint32_t*)&Vh[nr + kb + 2 * tq];
                bh2[1] = *(const uint32_t*)&Vh[nr + kb + 2 * tq + 8];
                bl2[0] = *(const uint32_t*)&Vl[nr + kb + 2 * tq];
                bl2[1] = *(const uint32_t*)&Vl[nr + kb + 2 * tq + 8];
#pragma unroll
                for (int mt = 0; mt < 2; mt++) {
                    mma16(ofrag[mt][nt], ah[mt], bh2);
                    mma16(ofrag[mt][nt], al[mt], bh2);
                    mma16(ofrag[mt][nt], ah[mt], bl2);
                }
            }
        }
    }

    // normalize + write [B,T,C]
    const int b = bh >> 4, h = bh & 15;
#pragma unroll
    for (int mt = 0; mt < 2; mt++) {
#pragma unroll
        for (int r = 0; r < 2; r++) {
            float inv = 1.f / lrow[mt][r];
            int q = Q0 + lqb + mt * 16 + r * 8 + g;
#pragma unroll
            for (int nt = 0; nt < 8; nt++) {
                float2 v = make_float2(ofrag[mt][nt][r * 2] * inv,
                                       ofrag[mt][nt][r * 2 + 1] * inv);
                *(float2*)&g_O[((size_t)b * 2048 + q) * 1024 + h * 64 + nt * 8 + tq * 2] = v;
            }
        }
    }
}

// ---------------------------------------------------------------------------
extern "C" void kernel_launch(void* const* d_in, const int* in_sizes, int n_in,
                              void* d_out, int out_size)
{
    const float* x     = (const float*)d_in[0];
    const float* qkv_w = (const float*)d_in[1];
    const float* qkv_b = (const float*)d_in[2];
    const float* out_w = (const float*)d_in[3];
    const float* out_b = (const float*)d_in[4];
    float* out = (float*)d_out;

    cudaFuncSetAttribute(gemm_bf16<0>, cudaFuncAttributeMaxDynamicSharedMemorySize, GEMM_SMEM);
    cudaFuncSetAttribute(gemm_bf16<1>, cudaFuncAttributeMaxDynamicSharedMemorySize, GEMM_SMEM);
    cudaFuncSetAttribute(attn_bf16, cudaFuncAttributeMaxDynamicSharedMemorySize, ATTN_SMEM);

    gemm_bf16<0><<<dim3(12, 32), 256, GEMM_SMEM>>>(x, qkv_w, qkv_b, nullptr);
    attn_bf16<<<dim3(8, 32), 256, ATTN_SMEM>>>();
    gemm_bf16<1><<<dim3(4, 32), 256, GEMM_SMEM>>>(nullptr, out_w, out_b, out);
}

// round 9
// speedup vs baseline: 2.6815x; 1.1807x over previous
#include <cuda_runtime.h>
#include <cuda_bf16.h>
#include <math.h>
#include <stdint.h>

// Problem constants: B=2, T=2048, C=1024, H=16, D=64
__device__ __align__(256) float g_Q[2u * 16 * 2048 * 64];  // [B,H,T,D]
__device__ __align__(256) float g_K[2u * 16 * 2048 * 64];
__device__ __align__(256) float g_V[2u * 16 * 2048 * 64];
__device__ __align__(256) float g_O[4096u * 1024];         // [B,T,C]

typedef __nv_bfloat16 bf16;

// ---------------------------------------------------------------------------
__device__ __forceinline__ void bfsplit(float x, bf16& h, bf16& l) {
    h = __float2bfloat16(x);
    l = __float2bfloat16(x - __bfloat162float(h));
}
__device__ __forceinline__ void split4(bf16* ph, bf16* pl, float4 v) {
    bf16 h[4], l[4];
    bfsplit(v.x, h[0], l[0]); bfsplit(v.y, h[1], l[1]);
    bfsplit(v.z, h[2], l[2]); bfsplit(v.w, h[3], l[3]);
    *(uint2*)ph = *(const uint2*)h;
    *(uint2*)pl = *(const uint2*)l;
}
// D += A*B  (m16n8k16, bf16 inputs, fp32 accum)
__device__ __forceinline__ void mma16(float* d, const uint32_t* a, const uint32_t* b) {
    asm volatile(
        "mma.sync.aligned.m16n8k16.row.col.f32.bf16.bf16.f32 "
        "{%0,%1,%2,%3},{%4,%5,%6,%7},{%8,%9},{%0,%1,%2,%3};"
        : "+f"(d[0]), "+f"(d[1]), "+f"(d[2]), "+f"(d[3])
        : "r"(a[0]), "r"(a[1]), "r"(a[2]), "r"(a[3]), "r"(b[0]), "r"(b[1]));
}
__device__ __forceinline__ uint32_t sptr(const void* p) {
    return (uint32_t)__cvta_generic_to_shared(p);
}
__device__ __forceinline__ void ldsm_x4(uint32_t* r, uint32_t a) {
    asm volatile("ldmatrix.sync.aligned.m8n8.x4.shared.b16 {%0,%1,%2,%3}, [%4];"
                 : "=r"(r[0]), "=r"(r[1]), "=r"(r[2]), "=r"(r[3]) : "r"(a));
}
__device__ __forceinline__ void ldsm_x2(uint32_t* r, uint32_t a) {
    asm volatile("ldmatrix.sync.aligned.m8n8.x2.shared.b16 {%0,%1}, [%2];"
                 : "=r"(r[0]), "=r"(r[1]) : "r"(a));
}
__device__ __forceinline__ void ldsm_x2t(uint32_t* r, uint32_t a) {
    asm volatile("ldmatrix.sync.aligned.m8n8.x2.trans.shared.b16 {%0,%1}, [%2];"
                 : "=r"(r[0]), "=r"(r[1]) : "r"(a));
}

// ---------------------------------------------------------------------------
// 3xBF16-split GEMM: out[m][n] = sum_k A[m,k]*Wt[n,k] + bias[n]
// Block 128(m) x 256(n), BK=16, 8 warps (2m x 4n), warp tile 64x64.
// Fragments via ldmatrix. Single __syncthreads per k-iter (distance-2 prefetch).
// ---------------------------------------------------------------------------
#define GS 24  // bf16 row stride: word stride 12 -> conflict-free ldmatrix phases
#define A_PL (2 * 128 * GS)
#define B_PL (2 * 256 * GS)
#define GEMM_SMEM ((2 * A_PL + 2 * B_PL) * (int)sizeof(bf16))  // 73,728 B

template <int MODE>
__global__ void __launch_bounds__(256, 1) gemm_bf16(const float* __restrict__ Aext,
                                                    const float* __restrict__ Wt,
                                                    const float* __restrict__ bias,
                                                    float* __restrict__ Out)
{
    const float* A = (MODE == 0) ? Aext : g_O;
    extern __shared__ bf16 gsm[];
    bf16* Ah = gsm;            // [2][128][GS]
    bf16* Al = Ah + A_PL;
    bf16* Bh = Al + A_PL;      // [2][256][GS]
    bf16* Bl = Bh + B_PL;

    const int tid = threadIdx.x;
    const int m0 = blockIdx.y * 128, n0 = blockIdx.x * 256;
    const int warp = tid >> 5, lane = tid & 31;
    const int wm = (warp >> 2) * 64, wn = (warp & 3) * 64;
    const int g = lane >> 2, tq = lane & 3;

    // ldmatrix lane addressing
    const int lrow16 = lane & 15;             // x4 row within 16
    const int lc8 = ((lane >> 4) & 1) * 8;    // x4 col half
    const int brow = lane & 7;                // x2 row within 8
    const int bc8 = ((lane >> 3) & 1) * 8;    // x2 col half

    const int rowL = tid >> 2;            // 0..63
    const int c4 = (tid & 3) * 4;
    const float* gA = A + (size_t)(m0 + rowL) * 1024 + c4;
    const float* gB = Wt + (size_t)(n0 + rowL) * 1024 + c4;

    float acc[4][8][4];
#pragma unroll
    for (int mt = 0; mt < 4; mt++)
#pragma unroll
        for (int nt = 0; nt < 8; nt++)
#pragma unroll
            for (int r = 0; r < 4; r++) acc[mt][nt][r] = 0.f;

    float4 ra[2], rb[4];
#pragma unroll
    for (int t = 0; t < 2; t++) ra[t] = *(const float4*)(gA + (size_t)t * 64 * 1024);
#pragma unroll
    for (int t = 0; t < 4; t++) rb[t] = *(const float4*)(gB + (size_t)t * 64 * 1024);
#pragma unroll
    for (int t = 0; t < 2; t++)
        split4(&Ah[(rowL + t * 64) * GS + c4], &Al[(rowL + t * 64) * GS + c4], ra[t]);
#pragma unroll
    for (int t = 0; t < 4; t++)
        split4(&Bh[(rowL + t * 64) * GS + c4], &Bl[(rowL + t * 64) * GS + c4], rb[t]);
#pragma unroll
    for (int t = 0; t < 2; t++) ra[t] = *(const float4*)(gA + (size_t)t * 64 * 1024 + 16);
#pragma unroll
    for (int t = 0; t < 4; t++) rb[t] = *(const float4*)(gB + (size_t)t * 64 * 1024 + 16);
    __syncthreads();

    for (int kt = 0; kt < 64; kt++) {
        const int buf = kt & 1;
        const int abase = (buf ^ 1) * 128 * GS;
        const int bbase = (buf ^ 1) * 256 * GS;
        if (kt < 63) {
#pragma unroll
            for (int t = 0; t < 2; t++)
                split4(&Ah[abase + (rowL + t * 64) * GS + c4],
                       &Al[abase + (rowL + t * 64) * GS + c4], ra[t]);
#pragma unroll
            for (int t = 0; t < 4; t++)
                split4(&Bh[bbase + (rowL + t * 64) * GS + c4],
                       &Bl[bbase + (rowL + t * 64) * GS + c4], rb[t]);
        }
        if (kt < 62) {
            int k0 = (kt + 2) * 16;
#pragma unroll
            for (int t = 0; t < 2; t++) ra[t] = *(const float4*)(gA + (size_t)t * 64 * 1024 + k0);
#pragma unroll
            for (int t = 0; t < 4; t++) rb[t] = *(const float4*)(gB + (size_t)t * 64 * 1024 + k0);
        }
        const int ab = buf * 128 * GS;
        const int bb = buf * 256 * GS;
        // A fragments via ldmatrix.x4 (hi+lo, 4 m-tiles)
        uint32_t Ahf[4][4], Alf[4][4];
#pragma unroll
        for (int mt = 0; mt < 4; mt++) {
            int r0 = (wm + mt * 16 + lrow16) * GS + lc8;
            ldsm_x4(Ahf[mt], sptr(&Ah[ab + r0]));
            ldsm_x4(Alf[mt], sptr(&Al[ab + r0]));
        }
        // B fragments in two halves (register cap), ldmatrix.x2
#pragma unroll
        for (int nh = 0; nh < 2; nh++) {
            uint32_t Bhf[4][2], Blf[4][2];
#pragma unroll
            for (int j = 0; j < 4; j++) {
                int c0r = (wn + (nh * 4 + j) * 8 + brow) * GS + bc8;
                ldsm_x2(Bhf[j], sptr(&Bh[bb + c0r]));
                ldsm_x2(Blf[j], sptr(&Bl[bb + c0r]));
            }
#pragma unroll
            for (int mt = 0; mt < 4; mt++)
#pragma unroll
                for (int j = 0; j < 4; j++) {
                    float* d = acc[mt][nh * 4 + j];
                    mma16(d, Ahf[mt], Bhf[j]);
                    mma16(d, Alf[mt], Bhf[j]);
                    mma16(d, Ahf[mt], Blf[j]);
                }
        }
        if (kt < 63) __syncthreads();
    }

    // epilogue
#pragma unroll
    for (int mt = 0; mt < 4; mt++) {
#pragma unroll
        for (int rr = 0; rr < 2; rr++) {
            int m = m0 + wm + mt * 16 + g + rr * 8;
#pragma unroll
            for (int nt = 0; nt < 8; nt++) {
#pragma unroll
                for (int cc = 0; cc < 2; cc++) {
                    int n = n0 + wn + nt * 8 + tq * 2 + cc;
                    float v = acc[mt][nt][rr * 2 + cc] + bias[n];
                    if (MODE == 0) {
                        int bb2 = m >> 11, tt = m & 2047;
                        int which = n >> 10, c = n & 1023, hh = c >> 6, dd = c & 63;
                        float* dst = (which == 0) ? g_Q : (which == 1) ? g_K : g_V;
                        dst[(((size_t)bb2 * 16 + hh) * 2048 + tt) * 64 + dd] = v;
                    } else {
                        Out[(size_t)m * 1024 + n] = v;
                    }
                }
            }
        }
    }
}

// ---------------------------------------------------------------------------
// Flash attention, 3xBF16 split. Block = 256 threads (8 warps), 256 q-rows,
// warp q-tile 32 rows. V stored NATURAL [k][d]; PV B-frags via ldmatrix.trans.
// Q/K/P fragments via ldmatrix.
// ---------------------------------------------------------------------------
#define AS 72                 // bf16 stride: word stride 36 -> conflict-free phases
#define KPLANE (64 * AS)
#define QPLANE (256 * AS)
#define ATTN_SMEM ((4 * QPLANE + 4 * KPLANE) * (int)sizeof(bf16))  // 184,320 B

__global__ void __launch_bounds__(256) attn_bf16()
{
    extern __shared__ bf16 smb[];
    bf16* Qh = smb;              bf16* Ql = Qh + QPLANE;   // [256][AS]
    bf16* Kh = Ql + QPLANE;      bf16* Kl = Kh + KPLANE;   // [64][AS]  ([key][k])
    bf16* Vh = Kl + KPLANE;      bf16* Vl = Vh + KPLANE;   // [64][AS]  ([k][d] natural)
    bf16* Ph = Vl + KPLANE;      bf16* Pl = Ph + QPLANE;   // [256][AS]

    const int tid = threadIdx.x;
    const int qt = gridDim.x - 1 - blockIdx.x;   // heavy blocks first
    const int bh = blockIdx.y;
    const int Q0 = qt * 256;
    const float* Qg = g_Q + (size_t)bh * 2048 * 64;
    const float* Kg = g_K + (size_t)bh * 2048 * 64;
    const float* Vg = g_V + (size_t)bh * 2048 * 64;

    const int warp = tid >> 5, lane = tid & 31;
    const int g = lane >> 2, tq = lane & 3;
    const int lqb = warp * 32;
    const int qwmin = Q0 + lqb;

    const int lrow16 = lane & 15;
    const int lc8 = ((lane >> 4) & 1) * 8;
    const int brow = lane & 7;
    const int bc8 = ((lane >> 3) & 1) * 8;

    // load + split Q tile [256][64]
#pragma unroll
    for (int t = 0; t < 16; t++) {
        int lf = tid + t * 256, q = lf >> 4, d4 = (lf & 15) * 4;
        split4(&Qh[q * AS + d4], &Ql[q * AS + d4],
               *(const float4*)(Qg + (size_t)(Q0 + q) * 64 + d4));
    }

    float ofrag[2][8][4];
#pragma unroll
    for (int mt = 0; mt < 2; mt++)
#pragma unroll
        for (int nt = 0; nt < 8; nt++)
#pragma unroll
            for (int r = 0; r < 4; r++) ofrag[mt][nt][r] = 0.f;
    float mrow[2][2], lrow[2][2];
#pragma unroll
    for (int mt = 0; mt < 2; mt++)
#pragma unroll
        for (int r = 0; r < 2; r++) { mrow[mt][r] = -INFINITY; lrow[mt][r] = 0.f; }

    const int ktmax = 4 * qt + 3;
    for (int kt = 0; kt <= ktmax; kt++) {
        __syncthreads();  // K/V planes safe to overwrite (orders Q load at kt=0)
#pragma unroll
        for (int t = 0; t < 4; t++) {
            int lf = tid + t * 256, kk = lf >> 4, d4 = (lf & 15) * 4;
            split4(&Kh[kk * AS + d4], &Kl[kk * AS + d4],
                   *(const float4*)(Kg + (size_t)(kt * 64 + kk) * 64 + d4));
            // V natural: same conflict-free row-contiguous staging as K
            split4(&Vh[kk * AS + d4], &Vl[kk * AS + d4],
                   *(const float4*)(Vg + (size_t)(kt * 64 + kk) * 64 + d4));
        }
        __syncthreads();

        const int k0g = kt * 64;
        if (k0g > qwmin + 31) continue;
        const bool needmask = (k0g + 63 > qwmin);

        // S = Q K^T  (m32 x n64 x k64 per warp)
        float sfrag[2][8][4];
#pragma unroll
        for (int mt = 0; mt < 2; mt++)
#pragma unroll
            for (int nt = 0; nt < 8; nt++)
#pragma unroll
                for (int r = 0; r < 4; r++) sfrag[mt][nt][r] = 0.f;

#pragma unroll
        for (int k16 = 0; k16 < 4; k16++) {
            int kb = k16 * 16;
            uint32_t ah[2][4], al[2][4];
#pragma unroll
            for (int mt = 0; mt < 2; mt++) {
                int r0 = (lqb + mt * 16 + lrow16) * AS + kb + lc8;
                ldsm_x4(ah[mt], sptr(&Qh[r0]));
                ldsm_x4(al[mt], sptr(&Ql[r0]));
            }
#pragma unroll
            for (int nt = 0; nt < 8; nt++) {
                int nr = (nt * 8 + brow) * AS + kb + bc8;
                uint32_t bh2[2], bl2[2];
                ldsm_x2(bh2, sptr(&Kh[nr]));
                ldsm_x2(bl2, sptr(&Kl[nr]));
#pragma unroll
                for (int mt = 0; mt < 2; mt++) {
                    mma16(sfrag[mt][nt], ah[mt], bh2);
                    mma16(sfrag[mt][nt], al[mt], bh2);
                    mma16(sfrag[mt][nt], ah[mt], bl2);
                }
            }
        }

        // softmax on fragments
#pragma unroll
        for (int mt = 0; mt < 2; mt++) {
#pragma unroll
            for (int r = 0; r < 2; r++) {
                int lq = lqb + mt * 16 + r * 8 + g;
                int qglob = Q0 + lq;
                float rm = -INFINITY;
#pragma unroll
                for (int nt = 0; nt < 8; nt++) {
#pragma unroll
                    for (int cc = 0; cc < 2; cc++) {
                        float sv = sfrag[mt][nt][r * 2 + cc] * 0.125f;  // 1/sqrt(64)
                        int keyg = k0g + nt * 8 + tq * 2 + cc;
                        if (needmask && keyg > qglob) sv = -INFINITY;
                        sfrag[mt][nt][r * 2 + cc] = sv;
                        rm = fmaxf(rm, sv);
                    }
                }
                rm = fmaxf(rm, __shfl_xor_sync(0xffffffffu, rm, 1));
                rm = fmaxf(rm, __shfl_xor_sync(0xffffffffu, rm, 2));
                float mnew = fmaxf(mrow[mt][r], rm);
                float esc = __expf(mrow[mt][r] - mnew);
                float rs = 0.f;
#pragma unroll
                for (int nt = 0; nt < 8; nt++) {
                    float p0 = __expf(sfrag[mt][nt][r * 2] - mnew);
                    float p1 = __expf(sfrag[mt][nt][r * 2 + 1] - mnew);
                    union { bf16 h[2]; uint32_t u; } hw, lw;
                    hw.h[0] = __float2bfloat16(p0);
                    hw.h[1] = __float2bfloat16(p1);
                    lw.h[0] = __float2bfloat16(p0 - __bfloat162float(hw.h[0]));
                    lw.h[1] = __float2bfloat16(p1 - __bfloat162float(hw.h[1]));
                    int off = lq * AS + nt * 8 + tq * 2;
                    *(uint32_t*)&Ph[off] = hw.u;
                    *(uint32_t*)&Pl[off] = lw.u;
                    rs += p0 + p1;
                }
                rs += __shfl_xor_sync(0xffffffffu, rs, 1);
                rs += __shfl_xor_sync(0xffffffffu, rs, 2);
                lrow[mt][r] = lrow[mt][r] * esc + rs;
                mrow[mt][r] = mnew;
#pragma unroll
                for (int nt = 0; nt < 8; nt++) {
                    ofrag[mt][nt][r * 2] *= esc;
                    ofrag[mt][nt][r * 2 + 1] *= esc;
                }
            }
        }
        __syncwarp();  // P rows are warp-private

        // O += P V  (m32 x n64 x k64); V B-frags via ldmatrix.x2.trans
#pragma unroll
        for (int k16 = 0; k16 < 4; k16++) {
            int kb = k16 * 16;
            uint32_t ah[2][4], al[2][4];
#pragma unroll
            for (int mt = 0; mt < 2; mt++) {
                int r0 = (lqb + mt * 16 + lrow16) * AS + kb + lc8;
                ldsm_x4(ah[mt], sptr(&Ph[r0]));
                ldsm_x4(al[mt], sptr(&Pl[r0]));
            }
#pragma unroll
            for (int nt = 0; nt < 8; nt++) {
                int vr = (kb + lrow16) * AS + nt * 8;
                uint32_t bh2[2], bl2[2];
                ldsm_x2t(bh2, sptr(&Vh[vr]));
                ldsm_x2t(bl2, sptr(&Vl[vr]));
#pragma unroll
                for (int mt = 0; mt < 2; mt++) {
                    mma16(ofrag[mt][nt], ah[mt], bh2);
                    mma16(ofrag[mt][nt], al[mt], bh2);
                    mma16(ofrag[mt][nt], ah[mt], bl2);
                }
            }
        }
    }

    // normalize + write [B,T,C]
    const int b = bh >> 4, h = bh & 15;
#pragma unroll
    for (int mt = 0; mt < 2; mt++) {
#pragma unroll
        for (int r = 0; r < 2; r++) {
            float inv = 1.f / lrow[mt][r];
            int q = Q0 + lqb + mt * 16 + r * 8 + g;
#pragma unroll
            for (int nt = 0; nt < 8; nt++) {
                float2 v = make_float2(ofrag[mt][nt][r * 2] * inv,
                                       ofrag[mt][nt][r * 2 + 1] * inv);
                *(float2*)&g_O[((size_t)b * 2048 + q) * 1024 + h * 64 + nt * 8 + tq * 2] = v;
            }
        }
    }
}

// ---------------------------------------------------------------------------
extern "C" void kernel_launch(void* const* d_in, const int* in_sizes, int n_in,
                              void* d_out, int out_size)
{
    const float* x     = (const float*)d_in[0];
    const float* qkv_w = (const float*)d_in[1];
    const float* qkv_b = (const float*)d_in[2];
    const float* out_w = (const float*)d_in[3];
    const float* out_b = (const float*)d_in[4];
    float* out = (float*)d_out;

    cudaFuncSetAttribute(gemm_bf16<0>, cudaFuncAttributeMaxDynamicSharedMemorySize, GEMM_SMEM);
    cudaFuncSetAttribute(gemm_bf16<1>, cudaFuncAttributeMaxDynamicSharedMemorySize, GEMM_SMEM);
    cudaFuncSetAttribute(attn_bf16, cudaFuncAttributeMaxDynamicSharedMemorySize, ATTN_SMEM);

    gemm_bf16<0><<<dim3(12, 32), 256, GEMM_SMEM>>>(x, qkv_w, qkv_b, nullptr);
    attn_bf16<<<dim3(8, 32), 256, ATTN_SMEM>>>();
    gemm_bf16<1><<<dim3(4, 32), 256, GEMM_SMEM>>>(nullptr, out_w, out_b, out);
}